// round 2
// baseline (speedup 1.0000x reference)
#include <cuda_runtime.h>
#include <math.h>

#define B_   2
#define T_   2048
#define D_   1024
#define NH_  32
#define HD_  32
#define M_   (B_ * T_)          // 4096 rows

// ---------------- scratch (allocation-free: __device__ globals) --------------
__device__ float g_q[M_ * D_];
__device__ float g_k[M_ * D_];
__device__ float g_v[M_ * D_];
__device__ float g_y[M_ * D_];

// ---------------- tiled fp32 GEMM: C[M,N] = A[M,K] @ W[N,K]^T ---------------
// BM=BN=64, BK=16, 256 threads, 4x4 microtile per thread.
__global__ void __launch_bounds__(256) gemm_nt(const float* __restrict__ A,
                                               const float* __restrict__ W,
                                               float* __restrict__ C,
                                               int M, int N, int K) {
    __shared__ float As[16][64];
    __shared__ float Ws[16][64];

    const int tid = threadIdx.x;
    const int m0 = blockIdx.y * 64;
    const int n0 = blockIdx.x * 64;
    const int lr = tid >> 2;           // 0..63
    const int lc = (tid & 3) << 2;     // 0,4,8,12
    const int ty = tid >> 4;           // 0..15
    const int tx = tid & 15;           // 0..15

    float acc[4][4] = {};

    const float* Ap = A + (size_t)(m0 + lr) * K + lc;
    const float* Wp = W + (size_t)(n0 + lr) * K + lc;

    for (int k0 = 0; k0 < K; k0 += 16) {
        float4 av = *(const float4*)(Ap + k0);
        float4 wv = *(const float4*)(Wp + k0);
        As[lc + 0][lr] = av.x; As[lc + 1][lr] = av.y;
        As[lc + 2][lr] = av.z; As[lc + 3][lr] = av.w;
        Ws[lc + 0][lr] = wv.x; Ws[lc + 1][lr] = wv.y;
        Ws[lc + 2][lr] = wv.z; Ws[lc + 3][lr] = wv.w;
        __syncthreads();

        #pragma unroll
        for (int k = 0; k < 16; k++) {
            float4 a4 = *(const float4*)&As[k][ty << 2];
            float4 b4 = *(const float4*)&Ws[k][tx << 2];
            float a[4] = {a4.x, a4.y, a4.z, a4.w};
            float b[4] = {b4.x, b4.y, b4.z, b4.w};
            #pragma unroll
            for (int i = 0; i < 4; i++)
                #pragma unroll
                for (int j = 0; j < 4; j++)
                    acc[i][j] += a[i] * b[j];
        }
        __syncthreads();
    }

    #pragma unroll
    for (int i = 0; i < 4; i++) {
        float4 o = make_float4(acc[i][0], acc[i][1], acc[i][2], acc[i][3]);
        *(float4*)&C[(size_t)(m0 + (ty << 2) + i) * N + n0 + (tx << 2)] = o;
    }
}

// ---------------- per-head RMSNorm + RoPE (+ optional gain) ------------------
// one warp per (row, head); row = b*T + t; head h occupies cols [h*32, h*32+32)
__global__ void __launch_bounds__(256) norm_rope(float* __restrict__ t,
                                                 const float* __restrict__ cosb,
                                                 const float* __restrict__ sinb,
                                                 const float* __restrict__ gain,
                                                 int useGain) {
    int warp = (blockIdx.x * blockDim.x + threadIdx.x) >> 5;
    int lane = threadIdx.x & 31;
    if (warp >= M_ * NH_) return;
    int row = warp >> 5;       // 0..4095
    int h   = warp & 31;
    int tp  = row & (T_ - 1);  // position within sequence

    float* p = t + (size_t)row * D_ + h * HD_;
    float v = p[lane];

    float ss = v * v;
    #pragma unroll
    for (int off = 16; off > 0; off >>= 1)
        ss += __shfl_xor_sync(0xffffffffu, ss, off);

    float r = rsqrtf(ss * (1.0f / HD_) + 1e-6f);
    float vn = v * r;

    float other = __shfl_xor_sync(0xffffffffu, vn, 16);
    int dd = lane & 15;
    float c = cosb[tp * 16 + dd];
    float s = sinb[tp * 16 + dd];
    float out = (lane < 16) ? (vn * c - other * s) : (vn * c + other * s);
    if (useGain) out *= gain[h];
    p[lane] = out;
}

// ---------------- causal flash attention -------------------------------------
// grid (T/64, B*NH); 256 threads; BQ=BK=64, HD=32
__global__ void __launch_bounds__(256) flash(const float* __restrict__ q,
                                             const float* __restrict__ k,
                                             const float* __restrict__ v,
                                             float* __restrict__ y) {
    __shared__ float qs[64][33];
    __shared__ float ks[64][33];
    __shared__ float vs[64][33];
    __shared__ float ps[64][66];

    const int qb = blockIdx.x;
    const int bh = blockIdx.y;
    const int tid = threadIdx.x;
    const int ty = tid >> 4, tx = tid & 15;
    const float scale = 0.17677669529663687f;   // 1/sqrt(32)

    const size_t base = ((size_t)(bh >> 5) * T_) * D_ + (size_t)(bh & 31) * HD_;

    // load Q tile [64][32]
    {
        int r = tid >> 2;
        int c = (tid & 3) << 3;
        const float* gp = q + base + (size_t)(qb * 64 + r) * D_ + c;
        #pragma unroll
        for (int i = 0; i < 8; i++) qs[r][c + i] = gp[i];
    }

    float m[4], l[4] = {0, 0, 0, 0}, o[4][2] = {};
    #pragma unroll
    for (int i = 0; i < 4; i++) m[i] = -1e30f;

    for (int jb = 0; jb <= qb; jb++) {
        __syncthreads();
        {   // load K,V tiles
            int r = tid >> 2;
            int c = (tid & 3) << 3;
            const float* kp = k + base + (size_t)(jb * 64 + r) * D_ + c;
            const float* vp = v + base + (size_t)(jb * 64 + r) * D_ + c;
            #pragma unroll
            for (int i = 0; i < 8; i++) { ks[r][c + i] = kp[i]; vs[r][c + i] = vp[i]; }
        }
        __syncthreads();

        // S = Q K^T  (4x4 per thread)
        float s[4][4] = {};
        #pragma unroll
        for (int d = 0; d < 32; d++) {
            float a0 = qs[(ty << 2) + 0][d], a1 = qs[(ty << 2) + 1][d];
            float a2 = qs[(ty << 2) + 2][d], a3 = qs[(ty << 2) + 3][d];
            float b0 = ks[(tx << 2) + 0][d], b1 = ks[(tx << 2) + 1][d];
            float b2 = ks[(tx << 2) + 2][d], b3 = ks[(tx << 2) + 3][d];
            s[0][0] += a0 * b0; s[0][1] += a0 * b1; s[0][2] += a0 * b2; s[0][3] += a0 * b3;
            s[1][0] += a1 * b0; s[1][1] += a1 * b1; s[1][2] += a1 * b2; s[1][3] += a1 * b3;
            s[2][0] += a2 * b0; s[2][1] += a2 * b1; s[2][2] += a2 * b2; s[2][3] += a2 * b3;
            s[3][0] += a3 * b0; s[3][1] += a3 * b1; s[3][2] += a3 * b2; s[3][3] += a3 * b3;
        }

        // scale + causal mask (only diagonal block needs masking)
        if (jb == qb) {
            #pragma unroll
            for (int i = 0; i < 4; i++)
                #pragma unroll
                for (int j = 0; j < 4; j++)
                    s[i][j] = ((ty << 2) + i >= (tx << 2) + j) ? s[i][j] * scale : -1e30f;
        } else {
            #pragma unroll
            for (int i = 0; i < 4; i++)
                #pragma unroll
                for (int j = 0; j < 4; j++)
                    s[i][j] *= scale;
        }

        // online softmax update
        #pragma unroll
        for (int i = 0; i < 4; i++) {
            float mx = fmaxf(fmaxf(s[i][0], s[i][1]), fmaxf(s[i][2], s[i][3]));
            #pragma unroll
            for (int off = 1; off < 16; off <<= 1)
                mx = fmaxf(mx, __shfl_xor_sync(0xffffffffu, mx, off));
            float mn = fmaxf(m[i], mx);
            float al = __expf(m[i] - mn);
            float p0 = __expf(s[i][0] - mn);
            float p1 = __expf(s[i][1] - mn);
            float p2 = __expf(s[i][2] - mn);
            float p3 = __expf(s[i][3] - mn);
            float sum = p0 + p1 + p2 + p3;
            #pragma unroll
            for (int off = 1; off < 16; off <<= 1)
                sum += __shfl_xor_sync(0xffffffffu, sum, off);
            l[i] = l[i] * al + sum;
            m[i] = mn;
            o[i][0] *= al; o[i][1] *= al;
            ps[(ty << 2) + i][(tx << 2) + 0] = p0;
            ps[(ty << 2) + i][(tx << 2) + 1] = p1;
            ps[(ty << 2) + i][(tx << 2) + 2] = p2;
            ps[(ty << 2) + i][(tx << 2) + 3] = p3;
        }
        __syncthreads();

        // O += P V : each thread 4 rows x 2 cols
        const int c0 = tx << 1;
        #pragma unroll 4
        for (int kk = 0; kk < 64; kk++) {
            float v0 = vs[kk][c0], v1 = vs[kk][c0 + 1];
            #pragma unroll
            for (int i = 0; i < 4; i++) {
                float pp = ps[(ty << 2) + i][kk];
                o[i][0] += pp * v0;
                o[i][1] += pp * v1;
            }
        }
    }

    // epilogue: divide by l, store to y in [B,T,NH,HD] row-major layout
    #pragma unroll
    for (int i = 0; i < 4; i++) {
        float inv = 1.0f / l[i];
        int qr = qb * 64 + (ty << 2) + i;
        float* yp = y + base + (size_t)qr * D_ + (tx << 1);
        yp[0] = o[i][0] * inv;
        yp[1] = o[i][1] * inv;
    }
}

// ---------------- launcher ----------------------------------------------------
extern "C" void kernel_launch(void* const* d_in, const int* in_sizes, int n_in,
                              void* d_out, int out_size) {
    const float* x     = (const float*)d_in[0];
    const float* Wq    = (const float*)d_in[1];
    const float* Wk    = (const float*)d_in[2];
    const float* Wv    = (const float*)d_in[3];
    const float* Wproj = (const float*)d_in[4];
    const float* gain  = (const float*)d_in[5];
    const float* cosb  = (const float*)d_in[6];
    const float* sinb  = (const float*)d_in[7];
    float* out = (float*)d_out;

    float *q, *k, *v, *y;
    cudaGetSymbolAddress((void**)&q, g_q);
    cudaGetSymbolAddress((void**)&k, g_k);
    cudaGetSymbolAddress((void**)&v, g_v);
    cudaGetSymbolAddress((void**)&y, g_y);

    dim3 gg(D_ / 64, M_ / 64);          // (16, 64)
    gemm_nt<<<gg, 256>>>(x, Wq, q, M_, D_, D_);
    gemm_nt<<<gg, 256>>>(x, Wk, k, M_, D_, D_);
    gemm_nt<<<gg, 256>>>(x, Wv, v, M_, D_, D_);

    int nwarps = M_ * NH_;              // 131072 warps
    norm_rope<<<nwarps / 8, 256>>>(q, cosb, sinb, gain, 1);
    norm_rope<<<nwarps / 8, 256>>>(k, cosb, sinb, gain, 0);

    flash<<<dim3(T_ / 64, B_ * NH_), 256>>>(q, k, v, y);

    gemm_nt<<<gg, 256>>>(y, Wproj, out, M_, D_, D_);
}

// round 7
// speedup vs baseline: 1.2287x; 1.2287x over previous
#include <cuda_runtime.h>
#include <math.h>

#define B_   2
#define T_   2048
#define D_   1024
#define NH_  32
#define HD_  32
#define M_   (B_ * T_)          // 4096 rows

// ---------------- scratch (allocation-free: __device__ globals) --------------
__device__ float g_q[M_ * D_];
__device__ float g_k[M_ * D_];
__device__ float g_v[M_ * D_];
__device__ float g_y[M_ * D_];

// ---------------- packed fp32x2 FMA (Blackwell) ------------------------------
__device__ __forceinline__ float2 ffma2(float2 a, float2 b, float2 c) {
    unsigned long long ua = *reinterpret_cast<unsigned long long*>(&a);
    unsigned long long ub = *reinterpret_cast<unsigned long long*>(&b);
    unsigned long long uc = *reinterpret_cast<unsigned long long*>(&c);
    asm("fma.rn.f32x2 %0, %1, %2, %0;" : "+l"(uc) : "l"(ua), "l"(ub));
    return *reinterpret_cast<float2*>(&uc);
}
__device__ __forceinline__ float2 dup2(float x) { return make_float2(x, x); }

// ---------------- tiled fp32 GEMM: C[M,N] = A[M,K] @ W[N,K]^T ---------------
// BM=BN=128, BK=16, 256 threads, 8x8 microtile, packed f32x2 FMA, reg prefetch.
__global__ void __launch_bounds__(256) gemm_nt(const float* __restrict__ A,
                                               const float* __restrict__ W,
                                               float* __restrict__ C,
                                               int M, int N, int K) {
    __shared__ float As[16][132];
    __shared__ float Ws[16][132];

    const int tid = threadIdx.x;
    const int m0 = blockIdx.y * 128;
    const int n0 = blockIdx.x * 128;
    const int lr = tid >> 2;           // 0..63
    const int lc = (tid & 3) << 2;     // 0,4,8,12
    const int ty = tid >> 4;           // 0..15
    const int tx = tid & 15;           // 0..15

    const float* Ap = A + (size_t)(m0 + lr) * K + lc;
    const float* Wp = W + (size_t)(n0 + lr) * K + lc;
    const size_t K64 = (size_t)64 * K;

    // prefetch first tile into registers
    float4 a0 = *(const float4*)(Ap);
    float4 a1 = *(const float4*)(Ap + K64);
    float4 w0 = *(const float4*)(Wp);
    float4 w1 = *(const float4*)(Wp + K64);

    float2 acc[8][4];
    #pragma unroll
    for (int i = 0; i < 8; i++)
        #pragma unroll
        for (int j = 0; j < 4; j++) acc[i][j] = make_float2(0.f, 0.f);

    for (int k0 = 0; k0 < K; k0 += 16) {
        // commit prefetched tile to smem (k-major)
        As[lc + 0][lr] = a0.x; As[lc + 1][lr] = a0.y;
        As[lc + 2][lr] = a0.z; As[lc + 3][lr] = a0.w;
        As[lc + 0][lr + 64] = a1.x; As[lc + 1][lr + 64] = a1.y;
        As[lc + 2][lr + 64] = a1.z; As[lc + 3][lr + 64] = a1.w;
        Ws[lc + 0][lr] = w0.x; Ws[lc + 1][lr] = w0.y;
        Ws[lc + 2][lr] = w0.z; Ws[lc + 3][lr] = w0.w;
        Ws[lc + 0][lr + 64] = w1.x; Ws[lc + 1][lr + 64] = w1.y;
        Ws[lc + 2][lr + 64] = w1.z; Ws[lc + 3][lr + 64] = w1.w;
        __syncthreads();

        if (k0 + 16 < K) {   // prefetch next tile
            a0 = *(const float4*)(Ap + k0 + 16);
            a1 = *(const float4*)(Ap + K64 + k0 + 16);
            w0 = *(const float4*)(Wp + k0 + 16);
            w1 = *(const float4*)(Wp + K64 + k0 + 16);
        }

        #pragma unroll
        for (int k = 0; k < 16; k++) {
            float4 x0 = *(const float4*)&As[k][ty << 3];
            float4 x1 = *(const float4*)&As[k][(ty << 3) + 4];
            float4 y0 = *(const float4*)&Ws[k][tx << 3];
            float4 y1 = *(const float4*)&Ws[k][(tx << 3) + 4];
            float av[8] = {x0.x, x0.y, x0.z, x0.w, x1.x, x1.y, x1.z, x1.w};
            float2 bp[4] = {{y0.x, y0.y}, {y0.z, y0.w}, {y1.x, y1.y}, {y1.z, y1.w}};
            #pragma unroll
            for (int i = 0; i < 8; i++) {
                float2 ad = dup2(av[i]);
                #pragma unroll
                for (int j = 0; j < 4; j++)
                    acc[i][j] = ffma2(ad, bp[j], acc[i][j]);
            }
        }
        __syncthreads();
    }

    #pragma unroll
    for (int i = 0; i < 8; i++) {
        float* cp = C + (size_t)(m0 + (ty << 3) + i) * N + n0 + (tx << 3);
        *(float4*)(cp)     = make_float4(acc[i][0].x, acc[i][0].y, acc[i][1].x, acc[i][1].y);
        *(float4*)(cp + 4) = make_float4(acc[i][2].x, acc[i][2].y, acc[i][3].x, acc[i][3].y);
    }
}

// ---------------- per-head RMSNorm + RoPE (+ optional gain) ------------------
__global__ void __launch_bounds__(256) norm_rope(float* __restrict__ t,
                                                 const float* __restrict__ cosb,
                                                 const float* __restrict__ sinb,
                                                 const float* __restrict__ gain,
                                                 int useGain) {
    int warp = (blockIdx.x * blockDim.x + threadIdx.x) >> 5;
    int lane = threadIdx.x & 31;
    if (warp >= M_ * NH_) return;
    int row = warp >> 5;
    int h   = warp & 31;
    int tp  = row & (T_ - 1);

    float* p = t + (size_t)row * D_ + h * HD_;
    float v = p[lane];

    float ss = v * v;
    #pragma unroll
    for (int off = 16; off > 0; off >>= 1)
        ss += __shfl_xor_sync(0xffffffffu, ss, off);

    float r = rsqrtf(ss * (1.0f / HD_) + 1e-6f);
    float vn = v * r;

    float other = __shfl_xor_sync(0xffffffffu, vn, 16);
    int dd = lane & 15;
    float c = cosb[tp * 16 + dd];
    float s = sinb[tp * 16 + dd];
    float out = (lane < 16) ? (vn * c - other * s) : (vn * c + other * s);
    if (useGain) out *= gain[h];
    p[lane] = out;
}

// ---------------- causal flash attention -------------------------------------
// grid (T/64, B*NH); 256 threads; BQ=BK=64, HD=32
__global__ void __launch_bounds__(256) flash(const float* __restrict__ q,
                                             const float* __restrict__ k,
                                             const float* __restrict__ v,
                                             float* __restrict__ y) {
    __shared__ float qs[32][68];   // [d][row]
    __shared__ float ks[32][68];   // [d][row]
    __shared__ float vs[64][36];   // [row][d]  (36 -> 144B row stride, 16B aligned)
    __shared__ float ps[64][68];   // [qrow][krow]

    const int qb = blockIdx.x;
    const int bh = blockIdx.y;
    const int tid = threadIdx.x;
    const int ty = tid >> 4, tx = tid & 15;
    const float scale = 0.17677669529663687f;   // 1/sqrt(32)

    const size_t base = ((size_t)(bh >> 5) * T_) * D_ + (size_t)(bh & 31) * HD_;

    // load Q tile, transposed to [d][row]
    {
        int r = tid >> 2;
        int c = (tid & 3) << 3;
        const float* gp = q + base + (size_t)(qb * 64 + r) * D_ + c;
        float4 u0 = *(const float4*)(gp);
        float4 u1 = *(const float4*)(gp + 4);
        qs[c + 0][r] = u0.x; qs[c + 1][r] = u0.y; qs[c + 2][r] = u0.z; qs[c + 3][r] = u0.w;
        qs[c + 4][r] = u1.x; qs[c + 5][r] = u1.y; qs[c + 6][r] = u1.z; qs[c + 7][r] = u1.w;
    }

    float m[4], l[4] = {0, 0, 0, 0};
    float2 o2[4];
    #pragma unroll
    for (int i = 0; i < 4; i++) { m[i] = -1e30f; o2[i] = make_float2(0.f, 0.f); }

    for (int jb = 0; jb <= qb; jb++) {
        __syncthreads();
        {   // load K (transposed) and V tiles
            int r = tid >> 2;
            int c = (tid & 3) << 3;
            const float* kp = k + base + (size_t)(jb * 64 + r) * D_ + c;
            const float* vp = v + base + (size_t)(jb * 64 + r) * D_ + c;
            float4 u0 = *(const float4*)(kp);
            float4 u1 = *(const float4*)(kp + 4);
            ks[c + 0][r] = u0.x; ks[c + 1][r] = u0.y; ks[c + 2][r] = u0.z; ks[c + 3][r] = u0.w;
            ks[c + 4][r] = u1.x; ks[c + 5][r] = u1.y; ks[c + 6][r] = u1.z; ks[c + 7][r] = u1.w;
            float4 w0 = *(const float4*)(vp);
            float4 w1 = *(const float4*)(vp + 4);
            *(float4*)&vs[r][c]     = w0;
            *(float4*)&vs[r][c + 4] = w1;
        }
        __syncthreads();

        // S = Q K^T  (4 rows x 4 cols per thread, packed f32x2)
        float2 s2[4][2];
        #pragma unroll
        for (int i = 0; i < 4; i++) { s2[i][0] = make_float2(0.f, 0.f); s2[i][1] = make_float2(0.f, 0.f); }
        #pragma unroll
        for (int d = 0; d < 32; d++) {
            float4 a4 = *(const float4*)&qs[d][ty << 2];
            float4 b4 = *(const float4*)&ks[d][tx << 2];
            float2 bp0 = make_float2(b4.x, b4.y);
            float2 bp1 = make_float2(b4.z, b4.w);
            float av[4] = {a4.x, a4.y, a4.z, a4.w};
            #pragma unroll
            for (int i = 0; i < 4; i++) {
                float2 ad = dup2(av[i]);
                s2[i][0] = ffma2(ad, bp0, s2[i][0]);
                s2[i][1] = ffma2(ad, bp1, s2[i][1]);
            }
        }

        // unpack, scale + causal mask
        float s[4][4];
        #pragma unroll
        for (int i = 0; i < 4; i++) {
            s[i][0] = s2[i][0].x; s[i][1] = s2[i][0].y;
            s[i][2] = s2[i][1].x; s[i][3] = s2[i][1].y;
        }
        if (jb == qb) {
            #pragma unroll
            for (int i = 0; i < 4; i++)
                #pragma unroll
                for (int j = 0; j < 4; j++)
                    s[i][j] = ((ty << 2) + i >= (tx << 2) + j) ? s[i][j] * scale : -1e30f;
        } else {
            #pragma unroll
            for (int i = 0; i < 4; i++)
                #pragma unroll
                for (int j = 0; j < 4; j++)
                    s[i][j] *= scale;
        }

        // online softmax update
        #pragma unroll
        for (int i = 0; i < 4; i++) {
            float mx = fmaxf(fmaxf(s[i][0], s[i][1]), fmaxf(s[i][2], s[i][3]));
            #pragma unroll
            for (int off = 1; off < 16; off <<= 1)
                mx = fmaxf(mx, __shfl_xor_sync(0xffffffffu, mx, off));
            float mn = fmaxf(m[i], mx);
            float al = __expf(m[i] - mn);
            float p0 = __expf(s[i][0] - mn);
            float p1 = __expf(s[i][1] - mn);
            float p2 = __expf(s[i][2] - mn);
            float p3 = __expf(s[i][3] - mn);
            float sum = p0 + p1 + p2 + p3;
            #pragma unroll
            for (int off = 1; off < 16; off <<= 1)
                sum += __shfl_xor_sync(0xffffffffu, sum, off);
            l[i] = l[i] * al + sum;
            m[i] = mn;
            o2[i].x *= al; o2[i].y *= al;
            *(float4*)&ps[(ty << 2) + i][tx << 2] = make_float4(p0, p1, p2, p3);
        }
        __syncthreads();

        // O += P V : 4 rows x 2 cols per thread, kk unrolled x4, packed FMA
        const int c0 = tx << 1;
        #pragma unroll 4
        for (int kk = 0; kk < 64; kk += 4) {
            float2 v0 = *(const float2*)&vs[kk + 0][c0];
            float2 v1 = *(const float2*)&vs[kk + 1][c0];
            float2 v2 = *(const float2*)&vs[kk + 2][c0];
            float2 v3 = *(const float2*)&vs[kk + 3][c0];
            #pragma unroll
            for (int i = 0; i < 4; i++) {
                float4 p4 = *(const float4*)&ps[(ty << 2) + i][kk];
                o2[i] = ffma2(dup2(p4.x), v0, o2[i]);
                o2[i] = ffma2(dup2(p4.y), v1, o2[i]);
                o2[i] = ffma2(dup2(p4.z), v2, o2[i]);
                o2[i] = ffma2(dup2(p4.w), v3, o2[i]);
            }
        }
    }

    // epilogue
    #pragma unroll
    for (int i = 0; i < 4; i++) {
        float inv = 1.0f / l[i];
        int qr = qb * 64 + (ty << 2) + i;
        float* yp = y + base + (size_t)qr * D_ + (tx << 1);
        yp[0] = o2[i].x * inv;
        yp[1] = o2[i].y * inv;
    }
}

// ---------------- launcher ----------------------------------------------------
extern "C" void kernel_launch(void* const* d_in, const int* in_sizes, int n_in,
                              void* d_out, int out_size) {
    const float* x     = (const float*)d_in[0];
    const float* Wq    = (const float*)d_in[1];
    const float* Wk    = (const float*)d_in[2];
    const float* Wv    = (const float*)d_in[3];
    const float* Wproj = (const float*)d_in[4];
    const float* gain  = (const float*)d_in[5];
    const float* cosb  = (const float*)d_in[6];
    const float* sinb  = (const float*)d_in[7];
    float* out = (float*)d_out;

    float *q, *k, *v, *y;
    cudaGetSymbolAddress((void**)&q, g_q);
    cudaGetSymbolAddress((void**)&k, g_k);
    cudaGetSymbolAddress((void**)&v, g_v);
    cudaGetSymbolAddress((void**)&y, g_y);

    dim3 gg(D_ / 128, M_ / 128);        // (8, 32)
    gemm_nt<<<gg, 256>>>(x, Wq, q, M_, D_, D_);
    gemm_nt<<<gg, 256>>>(x, Wk, k, M_, D_, D_);
    gemm_nt<<<gg, 256>>>(x, Wv, v, M_, D_, D_);

    int nwarps = M_ * NH_;
    norm_rope<<<nwarps / 8, 256>>>(q, cosb, sinb, gain, 1);
    norm_rope<<<nwarps / 8, 256>>>(k, cosb, sinb, gain, 0);

    flash<<<dim3(T_ / 64, B_ * NH_), 256>>>(q, k, v, y);

    gemm_nt<<<gg, 256>>>(y, Wproj, out, M_, D_, D_);
}

// round 11
// speedup vs baseline: 1.7989x; 1.4641x over previous
#include <cuda_runtime.h>
#include <cuda_bf16.h>
#include <math.h>
#include <stdint.h>

#define B_   2
#define T_   2048
#define D_   1024
#define NH_  32
#define HD_  32
#define M_   (B_ * T_)          // 4096 rows
#define K3_  3072               // split-bf16 concatenated K
#define ITERS_ (K3_ / 32)       // 96 k-chunks of 32

// ---------------- scratch (allocation-free: __device__ globals) --------------
__device__ float g_q[M_ * D_];
__device__ float g_k[M_ * D_];
__device__ float g_v[M_ * D_];
__device__ float g_y[M_ * D_];
__device__ __nv_bfloat16 g_xs[M_ * K3_];        // split x   [Ah|Al|Ah]
__device__ __nv_bfloat16 g_ys[M_ * K3_];        // split y
__device__ __nv_bfloat16 g_wqkv[3 * D_ * K3_];  // split [Wq;Wk;Wv]  [Wh|Wh|Wl]
__device__ __nv_bfloat16 g_wpro[D_ * K3_];      // split Wproj

// ---------------- PTX helpers -------------------------------------------------
__device__ __forceinline__ uint32_t smem_u32(const void* p) {
    return (uint32_t)__cvta_generic_to_shared(p);
}
__device__ __forceinline__ void cp_async16(uint32_t saddr, const void* gaddr) {
    asm volatile("cp.async.cg.shared.global [%0], [%1], 16;" :: "r"(saddr), "l"(gaddr));
}
__device__ __forceinline__ void cp_commit() {
    asm volatile("cp.async.commit_group;");
}
__device__ __forceinline__ void ldmatrix_x4(uint32_t& r0, uint32_t& r1, uint32_t& r2, uint32_t& r3,
                                            uint32_t a) {
    asm volatile("ldmatrix.sync.aligned.m8n8.x4.shared.b16 {%0,%1,%2,%3}, [%4];"
                 : "=r"(r0), "=r"(r1), "=r"(r2), "=r"(r3) : "r"(a));
}
__device__ __forceinline__ void mma16816(float* d, uint32_t a0, uint32_t a1, uint32_t a2, uint32_t a3,
                                         uint32_t b0, uint32_t b1) {
    asm volatile("mma.sync.aligned.m16n8k16.row.col.f32.bf16.bf16.f32 "
                 "{%0,%1,%2,%3}, {%4,%5,%6,%7}, {%8,%9}, {%0,%1,%2,%3};"
                 : "+f"(d[0]), "+f"(d[1]), "+f"(d[2]), "+f"(d[3])
                 : "r"(a0), "r"(a1), "r"(a2), "r"(a3), "r"(b0), "r"(b1));
}
// swizzled smem address: 128 rows x 4 units(16B); unit ^= (row>>1)&3
__device__ __forceinline__ uint32_t sw_addr(uint32_t base, int row, int unit) {
    return base + row * 64 + ((unit ^ ((row >> 1) & 3)) << 4);
}

// ---------------- split-bf16 conversion kernels -------------------------------
__global__ void __launch_bounds__(256) split_acts(const float* __restrict__ in,
                                                  __nv_bfloat16* __restrict__ out) {
    int i = blockIdx.x * 256 + threadIdx.x;
    int r = i >> 10, c = i & 1023;
    float x = in[i];
    __nv_bfloat16 h = __float2bfloat16(x);
    __nv_bfloat16 l = __float2bfloat16(x - __bfloat162float(h));
    __nv_bfloat16* o = out + (size_t)r * K3_ + c;
    o[0] = h; o[1024] = l; o[2048] = h;
}
__global__ void __launch_bounds__(256) split_wts(const float* __restrict__ in,
                                                 __nv_bfloat16* __restrict__ out) {
    int i = blockIdx.x * 256 + threadIdx.x;
    int r = i >> 10, c = i & 1023;
    float x = in[i];
    __nv_bfloat16 h = __float2bfloat16(x);
    __nv_bfloat16 l = __float2bfloat16(x - __bfloat162float(h));
    __nv_bfloat16* o = out + (size_t)r * K3_ + c;
    o[0] = h; o[1024] = h; o[2048] = l;
}

// ---------------- mma.sync bf16 GEMM: C[M,Ntot] = A'[M,K3] @ W'[Ntot,K3]^T ----
// 128x128x32 tiles, 8 warps (2x4), each warp 64x32 (4x4 m16n8k16 tiles),
// cp.async double-buffered smem, swizzled ldmatrix.
__global__ void __launch_bounds__(256)
gemm_bf16(const __nv_bfloat16* __restrict__ Abf,
          const __nv_bfloat16* __restrict__ Wbf,
          float* __restrict__ C0, float* __restrict__ C1, float* __restrict__ C2) {
    __shared__ __nv_bfloat16 sA[2][128 * 32];
    __shared__ __nv_bfloat16 sB[2][128 * 32];

    const int tid  = threadIdx.x;
    const int wid  = tid >> 5;
    const int lane = tid & 31;
    const int wm   = wid >> 2;          // 0..1  -> 64 rows
    const int wn   = wid & 3;           // 0..3  -> 32 cols
    const int m0   = blockIdx.y * 128;
    const int n0   = blockIdx.x * 128;

    const __nv_bfloat16* Ag = Abf + (size_t)m0 * K3_;
    const __nv_bfloat16* Wg = Wbf + (size_t)n0 * K3_;

    const uint32_t sa0 = smem_u32(&sA[0][0]);
    const uint32_t sa1 = smem_u32(&sA[1][0]);
    const uint32_t sb0 = smem_u32(&sB[0][0]);
    const uint32_t sb1 = smem_u32(&sB[1][0]);

    // loader: 512 x 16B units per tile; thread handles units tid, tid+256
    const int lrow0 = tid >> 1;                 // 0..127
    const int lu0   = (tid & 1) << 1;           // 0 or 2  (two consecutive units)

    float acc[4][4][4];
    #pragma unroll
    for (int i = 0; i < 4; i++)
        #pragma unroll
        for (int j = 0; j < 4; j++)
            #pragma unroll
            for (int e = 0; e < 4; e++) acc[i][j][e] = 0.f;

    // prologue: stage 0 and 1
    #pragma unroll
    for (int st = 0; st < 2; st++) {
        uint32_t sa = st ? sa1 : sa0;
        uint32_t sb = st ? sb1 : sb0;
        #pragma unroll
        for (int u = 0; u < 2; u++) {
            int unit = lu0 + u;
            cp_async16(sw_addr(sa, lrow0, unit), Ag + (size_t)lrow0 * K3_ + st * 32 + unit * 8);
            cp_async16(sw_addr(sb, lrow0, unit), Wg + (size_t)lrow0 * K3_ + st * 32 + unit * 8);
        }
        cp_commit();
    }

    for (int it = 0; it < ITERS_; it++) {
        asm volatile("cp.async.wait_group 1;");
        __syncthreads();

        const int buf = it & 1;
        const uint32_t sa = buf ? sa1 : sa0;
        const uint32_t sb = buf ? sb1 : sb0;

        #pragma unroll
        for (int ks = 0; ks < 2; ks++) {
            // A fragments: 4 m-tiles
            uint32_t af[4][4];
            #pragma unroll
            for (int mi = 0; mi < 4; mi++) {
                int row = wm * 64 + mi * 16 + (lane & 15);
                int unit = ks * 2 + (lane >> 4);
                ldmatrix_x4(af[mi][0], af[mi][1], af[mi][2], af[mi][3],
                            sw_addr(sa, row, unit));
            }
            // B fragments: 4 n-tiles via 2 x4-ldmatrix
            uint32_t bf[4][2];
            #pragma unroll
            for (int nh = 0; nh < 2; nh++) {
                int row = wn * 32 + nh * 16 + (lane & 7) + ((lane >> 4) << 3);
                int unit = ks * 2 + ((lane >> 3) & 1);
                uint32_t r0, r1, r2, r3;
                ldmatrix_x4(r0, r1, r2, r3, sw_addr(sb, row, unit));
                bf[nh * 2 + 0][0] = r0; bf[nh * 2 + 0][1] = r1;
                bf[nh * 2 + 1][0] = r2; bf[nh * 2 + 1][1] = r3;
            }
            #pragma unroll
            for (int mi = 0; mi < 4; mi++)
                #pragma unroll
                for (int ni = 0; ni < 4; ni++)
                    mma16816(acc[mi][ni], af[mi][0], af[mi][1], af[mi][2], af[mi][3],
                             bf[ni][0], bf[ni][1]);
        }
        __syncthreads();

        if (it + 2 < ITERS_) {
            #pragma unroll
            for (int u = 0; u < 2; u++) {
                int unit = lu0 + u;
                cp_async16(sw_addr(sa, lrow0, unit),
                           Ag + (size_t)lrow0 * K3_ + (it + 2) * 32 + unit * 8);
                cp_async16(sw_addr(sb, lrow0, unit),
                           Wg + (size_t)lrow0 * K3_ + (it + 2) * 32 + unit * 8);
            }
        }
        cp_commit();
    }

    // epilogue: write fp32 accumulators
    const int region = n0 >> 10;
    float* Cb = (region == 0) ? C0 : ((region == 1) ? C1 : C2);
    const int nloc = n0 & 1023;
    const int gid = lane >> 2;       // 0..7
    const int tig = lane & 3;        // 0..3
    #pragma unroll
    for (int mi = 0; mi < 4; mi++) {
        #pragma unroll
        for (int ni = 0; ni < 4; ni++) {
            int r0 = m0 + wm * 64 + mi * 16 + gid;
            int cc = nloc + wn * 32 + ni * 8 + tig * 2;
            *(float2*)&Cb[(size_t)r0 * D_ + cc]       = make_float2(acc[mi][ni][0], acc[mi][ni][1]);
            *(float2*)&Cb[(size_t)(r0 + 8) * D_ + cc] = make_float2(acc[mi][ni][2], acc[mi][ni][3]);
        }
    }
}

// ---------------- per-head RMSNorm + RoPE (+ optional gain) ------------------
__global__ void __launch_bounds__(256) norm_rope(float* __restrict__ t,
                                                 const float* __restrict__ cosb,
                                                 const float* __restrict__ sinb,
                                                 const float* __restrict__ gain,
                                                 int useGain) {
    int warp = (blockIdx.x * blockDim.x + threadIdx.x) >> 5;
    int lane = threadIdx.x & 31;
    if (warp >= M_ * NH_) return;
    int row = warp >> 5;
    int h   = warp & 31;
    int tp  = row & (T_ - 1);

    float* p = t + (size_t)row * D_ + h * HD_;
    float v = p[lane];

    float ss = v * v;
    #pragma unroll
    for (int off = 16; off > 0; off >>= 1)
        ss += __shfl_xor_sync(0xffffffffu, ss, off);

    float r = rsqrtf(ss * (1.0f / HD_) + 1e-6f);
    float vn = v * r;

    float other = __shfl_xor_sync(0xffffffffu, vn, 16);
    int dd = lane & 15;
    float c = cosb[tp * 16 + dd];
    float s = sinb[tp * 16 + dd];
    float out = (lane < 16) ? (vn * c - other * s) : (vn * c + other * s);
    if (useGain) out *= gain[h];
    p[lane] = out;
}

// ---------------- packed fp32x2 FMA (Blackwell) ------------------------------
__device__ __forceinline__ float2 ffma2(float2 a, float2 b, float2 c) {
    unsigned long long ua = *reinterpret_cast<unsigned long long*>(&a);
    unsigned long long ub = *reinterpret_cast<unsigned long long*>(&b);
    unsigned long long uc = *reinterpret_cast<unsigned long long*>(&c);
    asm("fma.rn.f32x2 %0, %1, %2, %0;" : "+l"(uc) : "l"(ua), "l"(ub));
    return *reinterpret_cast<float2*>(&uc);
}
__device__ __forceinline__ float2 dup2(float x) { return make_float2(x, x); }

// ---------------- causal flash attention -------------------------------------
__global__ void __launch_bounds__(256) flash(const float* __restrict__ q,
                                             const float* __restrict__ k,
                                             const float* __restrict__ v,
                                             float* __restrict__ y) {
    __shared__ float qs[32][68];   // [d][row]
    __shared__ float ks[32][68];   // [d][row]
    __shared__ float vs[64][36];   // [row][d]
    __shared__ float ps[64][68];   // [qrow][krow]

    const int qb = blockIdx.x;
    const int bh = blockIdx.y;
    const int tid = threadIdx.x;
    const int ty = tid >> 4, tx = tid & 15;
    const float scale = 0.17677669529663687f;   // 1/sqrt(32)

    const size_t base = ((size_t)(bh >> 5) * T_) * D_ + (size_t)(bh & 31) * HD_;

    {
        int r = tid >> 2;
        int c = (tid & 3) << 3;
        const float* gp = q + base + (size_t)(qb * 64 + r) * D_ + c;
        float4 u0 = *(const float4*)(gp);
        float4 u1 = *(const float4*)(gp + 4);
        qs[c + 0][r] = u0.x; qs[c + 1][r] = u0.y; qs[c + 2][r] = u0.z; qs[c + 3][r] = u0.w;
        qs[c + 4][r] = u1.x; qs[c + 5][r] = u1.y; qs[c + 6][r] = u1.z; qs[c + 7][r] = u1.w;
    }

    float m[4], l[4] = {0, 0, 0, 0};
    float2 o2[4];
    #pragma unroll
    for (int i = 0; i < 4; i++) { m[i] = -1e30f; o2[i] = make_float2(0.f, 0.f); }

    for (int jb = 0; jb <= qb; jb++) {
        __syncthreads();
        {
            int r = tid >> 2;
            int c = (tid & 3) << 3;
            const float* kp = k + base + (size_t)(jb * 64 + r) * D_ + c;
            const float* vp = v + base + (size_t)(jb * 64 + r) * D_ + c;
            float4 u0 = *(const float4*)(kp);
            float4 u1 = *(const float4*)(kp + 4);
            ks[c + 0][r] = u0.x; ks[c + 1][r] = u0.y; ks[c + 2][r] = u0.z; ks[c + 3][r] = u0.w;
            ks[c + 4][r] = u1.x; ks[c + 5][r] = u1.y; ks[c + 6][r] = u1.z; ks[c + 7][r] = u1.w;
            float4 w0 = *(const float4*)(vp);
            float4 w1 = *(const float4*)(vp + 4);
            *(float4*)&vs[r][c]     = w0;
            *(float4*)&vs[r][c + 4] = w1;
        }
        __syncthreads();

        float2 s2[4][2];
        #pragma unroll
        for (int i = 0; i < 4; i++) { s2[i][0] = make_float2(0.f, 0.f); s2[i][1] = make_float2(0.f, 0.f); }
        #pragma unroll
        for (int d = 0; d < 32; d++) {
            float4 a4 = *(const float4*)&qs[d][ty << 2];
            float4 b4 = *(const float4*)&ks[d][tx << 2];
            float2 bp0 = make_float2(b4.x, b4.y);
            float2 bp1 = make_float2(b4.z, b4.w);
            float av[4] = {a4.x, a4.y, a4.z, a4.w};
            #pragma unroll
            for (int i = 0; i < 4; i++) {
                float2 ad = dup2(av[i]);
                s2[i][0] = ffma2(ad, bp0, s2[i][0]);
                s2[i][1] = ffma2(ad, bp1, s2[i][1]);
            }
        }

        float s[4][4];
        #pragma unroll
        for (int i = 0; i < 4; i++) {
            s[i][0] = s2[i][0].x; s[i][1] = s2[i][0].y;
            s[i][2] = s2[i][1].x; s[i][3] = s2[i][1].y;
        }
        if (jb == qb) {
            #pragma unroll
            for (int i = 0; i < 4; i++)
                #pragma unroll
                for (int j = 0; j < 4; j++)
                    s[i][j] = ((ty << 2) + i >= (tx << 2) + j) ? s[i][j] * scale : -1e30f;
        } else {
            #pragma unroll
            for (int i = 0; i < 4; i++)
                #pragma unroll
                for (int j = 0; j < 4; j++)
                    s[i][j] *= scale;
        }

        #pragma unroll
        for (int i = 0; i < 4; i++) {
            float mx = fmaxf(fmaxf(s[i][0], s[i][1]), fmaxf(s[i][2], s[i][3]));
            #pragma unroll
            for (int off = 1; off < 16; off <<= 1)
                mx = fmaxf(mx, __shfl_xor_sync(0xffffffffu, mx, off));
            float mn = fmaxf(m[i], mx);
            float al = __expf(m[i] - mn);
            float p0 = __expf(s[i][0] - mn);
            float p1 = __expf(s[i][1] - mn);
            float p2 = __expf(s[i][2] - mn);
            float p3 = __expf(s[i][3] - mn);
            float sum = p0 + p1 + p2 + p3;
            #pragma unroll
            for (int off = 1; off < 16; off <<= 1)
                sum += __shfl_xor_sync(0xffffffffu, sum, off);
            l[i] = l[i] * al + sum;
            m[i] = mn;
            o2[i].x *= al; o2[i].y *= al;
            *(float4*)&ps[(ty << 2) + i][tx << 2] = make_float4(p0, p1, p2, p3);
        }
        __syncthreads();

        const int c0 = tx << 1;
        #pragma unroll 4
        for (int kk = 0; kk < 64; kk += 4) {
            float2 v0 = *(const float2*)&vs[kk + 0][c0];
            float2 v1 = *(const float2*)&vs[kk + 1][c0];
            float2 v2 = *(const float2*)&vs[kk + 2][c0];
            float2 v3 = *(const float2*)&vs[kk + 3][c0];
            #pragma unroll
            for (int i = 0; i < 4; i++) {
                float4 p4 = *(const float4*)&ps[(ty << 2) + i][kk];
                o2[i] = ffma2(dup2(p4.x), v0, o2[i]);
                o2[i] = ffma2(dup2(p4.y), v1, o2[i]);
                o2[i] = ffma2(dup2(p4.z), v2, o2[i]);
                o2[i] = ffma2(dup2(p4.w), v3, o2[i]);
            }
        }
    }

    #pragma unroll
    for (int i = 0; i < 4; i++) {
        float inv = 1.0f / l[i];
        int qr = qb * 64 + (ty << 2) + i;
        float* yp = y + base + (size_t)qr * D_ + (tx << 1);
        yp[0] = o2[i].x * inv;
        yp[1] = o2[i].y * inv;
    }
}

// ---------------- launcher ----------------------------------------------------
extern "C" void kernel_launch(void* const* d_in, const int* in_sizes, int n_in,
                              void* d_out, int out_size) {
    const float* x     = (const float*)d_in[0];
    const float* Wq    = (const float*)d_in[1];
    const float* Wk    = (const float*)d_in[2];
    const float* Wv    = (const float*)d_in[3];
    const float* Wproj = (const float*)d_in[4];
    const float* gain  = (const float*)d_in[5];
    const float* cosb  = (const float*)d_in[6];
    const float* sinb  = (const float*)d_in[7];
    float* out = (float*)d_out;

    float *q, *k, *v, *y;
    __nv_bfloat16 *xs, *ys, *wqkv, *wpro;
    cudaGetSymbolAddress((void**)&q, g_q);
    cudaGetSymbolAddress((void**)&k, g_k);
    cudaGetSymbolAddress((void**)&v, g_v);
    cudaGetSymbolAddress((void**)&y, g_y);
    cudaGetSymbolAddress((void**)&xs, g_xs);
    cudaGetSymbolAddress((void**)&ys, g_ys);
    cudaGetSymbolAddress((void**)&wqkv, g_wqkv);
    cudaGetSymbolAddress((void**)&wpro, g_wpro);

    // split conversions
    split_acts<<<(M_ * D_) / 256, 256>>>(x, xs);
    split_wts<<<(D_ * D_) / 256, 256>>>(Wq, wqkv);
    split_wts<<<(D_ * D_) / 256, 256>>>(Wk, wqkv + (size_t)D_ * K3_);
    split_wts<<<(D_ * D_) / 256, 256>>>(Wv, wqkv + (size_t)2 * D_ * K3_);
    split_wts<<<(D_ * D_) / 256, 256>>>(Wproj, wpro);

    // fused QKV GEMM: N = 3072 -> q | k | v
    gemm_bf16<<<dim3(3 * D_ / 128, M_ / 128), 256>>>(xs, wqkv, q, k, v);

    int nwarps = M_ * NH_;
    norm_rope<<<nwarps / 8, 256>>>(q, cosb, sinb, gain, 1);
    norm_rope<<<nwarps / 8, 256>>>(k, cosb, sinb, gain, 0);

    flash<<<dim3(T_ / 64, B_ * NH_), 256>>>(q, k, v, y);

    split_acts<<<(M_ * D_) / 256, 256>>>(y, ys);
    gemm_bf16<<<dim3(D_ / 128, M_ / 128), 256>>>(ys, wpro, out, out, out);
}

// round 14
// speedup vs baseline: 2.9818x; 1.6575x over previous
#include <cuda_runtime.h>
#include <cuda_bf16.h>
#include <math.h>
#include <stdint.h>

#define B_   2
#define T_   2048
#define D_   1024
#define NH_  32
#define HD_  32
#define M_   (B_ * T_)          // 4096 rows
#define K3_  3072               // split-bf16 concatenated K
#define ITERS_ (K3_ / 32)       // 96 k-chunks of 32

// ---------------- scratch (allocation-free: __device__ globals) --------------
__device__ float g_q[M_ * D_];
__device__ float g_k[M_ * D_];
__device__ float g_v[M_ * D_];
__device__ __nv_bfloat16 g_qh[M_ * D_], g_ql[M_ * D_];
__device__ __nv_bfloat16 g_kh[M_ * D_], g_kl[M_ * D_];
__device__ __nv_bfloat16 g_vh[M_ * D_], g_vl[M_ * D_];
__device__ __nv_bfloat16 g_xs[M_ * K3_];        // split x   [Ah|Al|Ah]
__device__ __nv_bfloat16 g_ys[M_ * K3_];        // split y   (written by flash)
__device__ __nv_bfloat16 g_wqkv[3 * D_ * K3_];  // split [Wq;Wk;Wv]  [Wh|Wh|Wl]
__device__ __nv_bfloat16 g_wpro[D_ * K3_];      // split Wproj

// ---------------- PTX helpers -------------------------------------------------
__device__ __forceinline__ uint32_t smem_u32(const void* p) {
    return (uint32_t)__cvta_generic_to_shared(p);
}
__device__ __forceinline__ void cp_async16(uint32_t saddr, const void* gaddr) {
    asm volatile("cp.async.cg.shared.global [%0], [%1], 16;" :: "r"(saddr), "l"(gaddr));
}
__device__ __forceinline__ void cp_commit() {
    asm volatile("cp.async.commit_group;");
}
__device__ __forceinline__ void cp_wait0() {
    asm volatile("cp.async.wait_group 0;");
}
__device__ __forceinline__ void ldm_x4(uint32_t* r, uint32_t a) {
    asm volatile("ldmatrix.sync.aligned.m8n8.x4.shared.b16 {%0,%1,%2,%3}, [%4];"
                 : "=r"(r[0]), "=r"(r[1]), "=r"(r[2]), "=r"(r[3]) : "r"(a));
}
__device__ __forceinline__ void ldm_x4_t(uint32_t* r, uint32_t a) {
    asm volatile("ldmatrix.sync.aligned.m8n8.x4.trans.shared.b16 {%0,%1,%2,%3}, [%4];"
                 : "=r"(r[0]), "=r"(r[1]), "=r"(r[2]), "=r"(r[3]) : "r"(a));
}
__device__ __forceinline__ void mma16816(float* d, const uint32_t* a, uint32_t b0, uint32_t b1) {
    asm volatile("mma.sync.aligned.m16n8k16.row.col.f32.bf16.bf16.f32 "
                 "{%0,%1,%2,%3}, {%4,%5,%6,%7}, {%8,%9}, {%0,%1,%2,%3};"
                 : "+f"(d[0]), "+f"(d[1]), "+f"(d[2]), "+f"(d[3])
                 : "r"(a[0]), "r"(a[1]), "r"(a[2]), "r"(a[3]), "r"(b0), "r"(b1));
}
// swizzled smem address: rows of 64B (4 x 16B units); unit ^= (row>>1)&3
__device__ __forceinline__ uint32_t sw_addr(uint32_t base, int row, int unit) {
    return base + row * 64 + ((unit ^ ((row >> 1) & 3)) << 4);
}
// pack two floats into hi(bf16x2) and lo(residual bf16x2)
__device__ __forceinline__ void pack_split(float x, float y, uint32_t& hi, uint32_t& lo) {
    __nv_bfloat162 hb = __floats2bfloat162_rn(x, y);
    hi = *reinterpret_cast<uint32_t*>(&hb);
    float2 hf = __bfloat1622float2(hb);
    __nv_bfloat162 lb = __floats2bfloat162_rn(x - hf.x, y - hf.y);
    lo = *reinterpret_cast<uint32_t*>(&lb);
}

// ---------------- split-bf16 conversion kernels -------------------------------
__global__ void __launch_bounds__(256) split_acts(const float* __restrict__ in,
                                                  __nv_bfloat16* __restrict__ out) {
    int i = blockIdx.x * 256 + threadIdx.x;
    int r = i >> 10, c = i & 1023;
    float x = in[i];
    __nv_bfloat16 h = __float2bfloat16(x);
    __nv_bfloat16 l = __float2bfloat16(x - __bfloat162float(h));
    __nv_bfloat16* o = out + (size_t)r * K3_ + c;
    o[0] = h; o[1024] = l; o[2048] = h;
}
__global__ void __launch_bounds__(256) split_wts(const float* __restrict__ in,
                                                 __nv_bfloat16* __restrict__ out) {
    int i = blockIdx.x * 256 + threadIdx.x;
    int r = i >> 10, c = i & 1023;
    float x = in[i];
    __nv_bfloat16 h = __float2bfloat16(x);
    __nv_bfloat16 l = __float2bfloat16(x - __bfloat162float(h));
    __nv_bfloat16* o = out + (size_t)r * K3_ + c;
    o[0] = h; o[1024] = h; o[2048] = l;
}
__global__ void __launch_bounds__(256) split_v(const float* __restrict__ in,
                                               __nv_bfloat16* __restrict__ oh,
                                               __nv_bfloat16* __restrict__ ol) {
    int i = blockIdx.x * 256 + threadIdx.x;
    float x = in[i];
    __nv_bfloat16 h = __float2bfloat16(x);
    oh[i] = h;
    ol[i] = __float2bfloat16(x - __bfloat162float(h));
}

// ---------------- mma.sync bf16 GEMM (unchanged from R11) ---------------------
__global__ void __launch_bounds__(256)
gemm_bf16(const __nv_bfloat16* __restrict__ Abf,
          const __nv_bfloat16* __restrict__ Wbf,
          float* __restrict__ C0, float* __restrict__ C1, float* __restrict__ C2) {
    __shared__ __nv_bfloat16 sA[2][128 * 32];
    __shared__ __nv_bfloat16 sB[2][128 * 32];

    const int tid  = threadIdx.x;
    const int wid  = tid >> 5;
    const int lane = tid & 31;
    const int wm   = wid >> 2;
    const int wn   = wid & 3;
    const int m0   = blockIdx.y * 128;
    const int n0   = blockIdx.x * 128;

    const __nv_bfloat16* Ag = Abf + (size_t)m0 * K3_;
    const __nv_bfloat16* Wg = Wbf + (size_t)n0 * K3_;

    const uint32_t sa0 = smem_u32(&sA[0][0]);
    const uint32_t sa1 = smem_u32(&sA[1][0]);
    const uint32_t sb0 = smem_u32(&sB[0][0]);
    const uint32_t sb1 = smem_u32(&sB[1][0]);

    const int lrow0 = tid >> 1;
    const int lu0   = (tid & 1) << 1;

    float acc[4][4][4];
    #pragma unroll
    for (int i = 0; i < 4; i++)
        #pragma unroll
        for (int j = 0; j < 4; j++)
            #pragma unroll
            for (int e = 0; e < 4; e++) acc[i][j][e] = 0.f;

    #pragma unroll
    for (int st = 0; st < 2; st++) {
        uint32_t sa = st ? sa1 : sa0;
        uint32_t sb = st ? sb1 : sb0;
        #pragma unroll
        for (int u = 0; u < 2; u++) {
            int unit = lu0 + u;
            cp_async16(sw_addr(sa, lrow0, unit), Ag + (size_t)lrow0 * K3_ + st * 32 + unit * 8);
            cp_async16(sw_addr(sb, lrow0, unit), Wg + (size_t)lrow0 * K3_ + st * 32 + unit * 8);
        }
        cp_commit();
    }

    for (int it = 0; it < ITERS_; it++) {
        asm volatile("cp.async.wait_group 1;");
        __syncthreads();

        const int buf = it & 1;
        const uint32_t sa = buf ? sa1 : sa0;
        const uint32_t sb = buf ? sb1 : sb0;

        #pragma unroll
        for (int ks = 0; ks < 2; ks++) {
            uint32_t af[4][4];
            #pragma unroll
            for (int mi = 0; mi < 4; mi++) {
                int row = wm * 64 + mi * 16 + (lane & 15);
                int unit = ks * 2 + (lane >> 4);
                ldm_x4(af[mi], sw_addr(sa, row, unit));
            }
            uint32_t bfr[4][2];
            #pragma unroll
            for (int nh = 0; nh < 2; nh++) {
                int row = wn * 32 + nh * 16 + (lane & 7) + ((lane >> 4) << 3);
                int unit = ks * 2 + ((lane >> 3) & 1);
                uint32_t r4[4];
                ldm_x4(r4, sw_addr(sb, row, unit));
                bfr[nh * 2 + 0][0] = r4[0]; bfr[nh * 2 + 0][1] = r4[1];
                bfr[nh * 2 + 1][0] = r4[2]; bfr[nh * 2 + 1][1] = r4[3];
            }
            #pragma unroll
            for (int mi = 0; mi < 4; mi++)
                #pragma unroll
                for (int ni = 0; ni < 4; ni++)
                    mma16816(acc[mi][ni], af[mi], bfr[ni][0], bfr[ni][1]);
        }
        __syncthreads();

        if (it + 2 < ITERS_) {
            #pragma unroll
            for (int u = 0; u < 2; u++) {
                int unit = lu0 + u;
                cp_async16(sw_addr(sa, lrow0, unit),
                           Ag + (size_t)lrow0 * K3_ + (it + 2) * 32 + unit * 8);
                cp_async16(sw_addr(sb, lrow0, unit),
                           Wg + (size_t)lrow0 * K3_ + (it + 2) * 32 + unit * 8);
            }
        }
        cp_commit();
    }

    const int region = n0 >> 10;
    float* Cb = (region == 0) ? C0 : ((region == 1) ? C1 : C2);
    const int nloc = n0 & 1023;
    const int gid = lane >> 2;
    const int tig = lane & 3;
    #pragma unroll
    for (int mi = 0; mi < 4; mi++) {
        #pragma unroll
        for (int ni = 0; ni < 4; ni++) {
            int r0 = m0 + wm * 64 + mi * 16 + gid;
            int cc = nloc + wn * 32 + ni * 8 + tig * 2;
            *(float2*)&Cb[(size_t)r0 * D_ + cc]       = make_float2(acc[mi][ni][0], acc[mi][ni][1]);
            *(float2*)&Cb[(size_t)(r0 + 8) * D_ + cc] = make_float2(acc[mi][ni][2], acc[mi][ni][3]);
        }
    }
}

// ---------------- per-head RMSNorm + RoPE -> split bf16 ------------------------
__global__ void __launch_bounds__(256) norm_rope_split(const float* __restrict__ t,
                                                       const float* __restrict__ cosb,
                                                       const float* __restrict__ sinb,
                                                       const float* __restrict__ gain,
                                                       int useGain,
                                                       __nv_bfloat16* __restrict__ oh,
                                                       __nv_bfloat16* __restrict__ ol) {
    int warp = (blockIdx.x * blockDim.x + threadIdx.x) >> 5;
    int lane = threadIdx.x & 31;
    if (warp >= M_ * NH_) return;
    int row = warp >> 5;
    int h   = warp & 31;
    int tp  = row & (T_ - 1);

    size_t idx = (size_t)row * D_ + h * HD_ + lane;
    float v = t[idx];

    float ss = v * v;
    #pragma unroll
    for (int off = 16; off > 0; off >>= 1)
        ss += __shfl_xor_sync(0xffffffffu, ss, off);

    float r = rsqrtf(ss * (1.0f / HD_) + 1e-6f);
    float vn = v * r;

    float other = __shfl_xor_sync(0xffffffffu, vn, 16);
    int dd = lane & 15;
    float c = cosb[tp * 16 + dd];
    float s = sinb[tp * 16 + dd];
    float out = (lane < 16) ? (vn * c - other * s) : (vn * c + other * s);
    if (useGain) out *= gain[h];

    __nv_bfloat16 hb = __float2bfloat16(out);
    oh[idx] = hb;
    ol[idx] = __float2bfloat16(out - __bfloat162float(hb));
}

// ---------------- tensor-core causal flash attention ---------------------------
// grid (T/64, B*NH); 128 threads (4 warps); BQ=BK=64, HD=32; split-bf16 mma.
__global__ void __launch_bounds__(128)
flash_tc(const __nv_bfloat16* __restrict__ qh, const __nv_bfloat16* __restrict__ ql,
         const __nv_bfloat16* __restrict__ kh, const __nv_bfloat16* __restrict__ kl,
         const __nv_bfloat16* __restrict__ vh, const __nv_bfloat16* __restrict__ vl,
         __nv_bfloat16* __restrict__ ys) {
    __shared__ __nv_bfloat16 sQh[64 * 32], sQl[64 * 32];
    __shared__ __nv_bfloat16 sKh[64 * 32], sKl[64 * 32];
    __shared__ __nv_bfloat16 sVh[64 * 32], sVl[64 * 32];

    const int tid = threadIdx.x, lane = tid & 31, w = tid >> 5;
    const int gid = lane >> 2, tig = lane & 3;
    const int qb = blockIdx.x, bh = blockIdx.y;
    const size_t rowQ = (size_t)(bh >> 5) * T_ + qb * 64;
    const int hoff = (bh & 31) * HD_;
    const float scale = 0.17677669529663687f;   // 1/sqrt(32)

    const uint32_t sqh = smem_u32(sQh), sql = smem_u32(sQl);
    const uint32_t skh = smem_u32(sKh), skl = smem_u32(sKl);
    const uint32_t svh = smem_u32(sVh), svl = smem_u32(sVl);

    // load Q tile halves (64 rows x 4 units each): 2 units per thread per array
    #pragma unroll
    for (int u = 0; u < 2; u++) {
        int id = tid * 2 + u;
        int un = id & 3, row = id >> 2;
        size_t go = (rowQ + row) * D_ + hoff + un * 8;
        cp_async16(sw_addr(sqh, row, un), qh + go);
        cp_async16(sw_addr(sql, row, un), ql + go);
    }
    cp_commit(); cp_wait0(); __syncthreads();

    // Q A-fragments (persist across KV loop)
    uint32_t qaf[2][4], qlf[2][4];
    #pragma unroll
    for (int ks = 0; ks < 2; ks++) {
        uint32_t addr = sw_addr(sqh, w * 16 + (lane & 15), ks * 2 + (lane >> 4));
        ldm_x4(qaf[ks], addr);
        addr = sw_addr(sql, w * 16 + (lane & 15), ks * 2 + (lane >> 4));
        ldm_x4(qlf[ks], addr);
    }

    float m0 = -1e30f, m1 = -1e30f, l0 = 0.f, l1 = 0.f;
    float O[4][4];
    #pragma unroll
    for (int j = 0; j < 4; j++)
        #pragma unroll
        for (int e = 0; e < 4; e++) O[j][e] = 0.f;

    for (int jb = 0; jb <= qb; jb++) {
        __syncthreads();
        const size_t rowK = (size_t)(bh >> 5) * T_ + jb * 64;
        #pragma unroll
        for (int u = 0; u < 2; u++) {
            int id = tid * 2 + u;
            int un = id & 3, row = id >> 2;
            size_t go = (rowK + row) * D_ + hoff + un * 8;
            cp_async16(sw_addr(skh, row, un), kh + go);
            cp_async16(sw_addr(skl, row, un), kl + go);
            cp_async16(sw_addr(svh, row, un), vh + go);
            cp_async16(sw_addr(svl, row, un), vl + go);
        }
        cp_commit(); cp_wait0(); __syncthreads();

        // ---- S = Q K^T  (split: QhKh + QlKh + QhKl) ----
        float st[8][4];
        #pragma unroll
        for (int j = 0; j < 8; j++)
            #pragma unroll
            for (int e = 0; e < 4; e++) st[j][e] = 0.f;

        #pragma unroll
        for (int g = 0; g < 4; g++) {
            #pragma unroll
            for (int ks = 0; ks < 2; ks++) {
                int brow = g * 16 + (lane & 7) + ((lane >> 4) << 3);
                int bun = ks * 2 + ((lane >> 3) & 1);
                uint32_t bh4[4], bl4[4];
                ldm_x4(bh4, sw_addr(skh, brow, bun));
                ldm_x4(bl4, sw_addr(skl, brow, bun));
                mma16816(st[2 * g],     qaf[ks], bh4[0], bh4[1]);
                mma16816(st[2 * g],     qlf[ks], bh4[0], bh4[1]);
                mma16816(st[2 * g],     qaf[ks], bl4[0], bl4[1]);
                mma16816(st[2 * g + 1], qaf[ks], bh4[2], bh4[3]);
                mma16816(st[2 * g + 1], qlf[ks], bh4[2], bh4[3]);
                mma16816(st[2 * g + 1], qaf[ks], bl4[2], bl4[3]);
            }
        }

        // ---- scale + causal mask ----
        const int rlo = w * 16 + gid, rhi = rlo + 8;
        if (jb == qb) {
            #pragma unroll
            for (int j = 0; j < 8; j++) {
                int c0 = j * 8 + 2 * tig;
                st[j][0] = (c0     <= rlo) ? st[j][0] * scale : -1e30f;
                st[j][1] = (c0 + 1 <= rlo) ? st[j][1] * scale : -1e30f;
                st[j][2] = (c0     <= rhi) ? st[j][2] * scale : -1e30f;
                st[j][3] = (c0 + 1 <= rhi) ? st[j][3] * scale : -1e30f;
            }
        } else {
            #pragma unroll
            for (int j = 0; j < 8; j++)
                #pragma unroll
                for (int e = 0; e < 4; e++) st[j][e] *= scale;
        }

        // ---- online softmax (rows rlo, rhi; full row = lane quad) ----
        float mx0 = -1e30f, mx1 = -1e30f;
        #pragma unroll
        for (int j = 0; j < 8; j++) {
            mx0 = fmaxf(mx0, fmaxf(st[j][0], st[j][1]));
            mx1 = fmaxf(mx1, fmaxf(st[j][2], st[j][3]));
        }
        mx0 = fmaxf(mx0, __shfl_xor_sync(0xffffffffu, mx0, 1));
        mx0 = fmaxf(mx0, __shfl_xor_sync(0xffffffffu, mx0, 2));
        mx1 = fmaxf(mx1, __shfl_xor_sync(0xffffffffu, mx1, 1));
        mx1 = fmaxf(mx1, __shfl_xor_sync(0xffffffffu, mx1, 2));

        float mn0 = fmaxf(m0, mx0), mn1 = fmaxf(m1, mx1);
        float al0 = __expf(m0 - mn0), al1 = __expf(m1 - mn1);
        float s0 = 0.f, s1 = 0.f;
        #pragma unroll
        for (int j = 0; j < 8; j++) {
            st[j][0] = __expf(st[j][0] - mn0); s0 += st[j][0];
            st[j][1] = __expf(st[j][1] - mn0); s0 += st[j][1];
            st[j][2] = __expf(st[j][2] - mn1); s1 += st[j][2];
            st[j][3] = __expf(st[j][3] - mn1); s1 += st[j][3];
        }
        s0 += __shfl_xor_sync(0xffffffffu, s0, 1);
        s0 += __shfl_xor_sync(0xffffffffu, s0, 2);
        s1 += __shfl_xor_sync(0xffffffffu, s1, 1);
        s1 += __shfl_xor_sync(0xffffffffu, s1, 2);
        l0 = l0 * al0 + s0; l1 = l1 * al1 + s1;
        m0 = mn0; m1 = mn1;

        #pragma unroll
        for (int j = 0; j < 4; j++) {
            O[j][0] *= al0; O[j][1] *= al0;
            O[j][2] *= al1; O[j][3] *= al1;
        }

        // ---- O += P V  (split: PhVh + PlVh + PhVl); V via ldmatrix.trans ----
        #pragma unroll
        for (int ks = 0; ks < 4; ks++) {
            const int t0 = 2 * ks, t1 = 2 * ks + 1;
            uint32_t pah[4], pal[4];
            pack_split(st[t0][0], st[t0][1], pah[0], pal[0]);
            pack_split(st[t0][2], st[t0][3], pah[1], pal[1]);
            pack_split(st[t1][0], st[t1][1], pah[2], pal[2]);
            pack_split(st[t1][2], st[t1][3], pah[3], pal[3]);

            #pragma unroll
            for (int jp = 0; jp < 2; jp++) {
                int vrow = ks * 16 + (lane & 15);
                int vun  = jp * 2 + (lane >> 4);
                uint32_t vh4[4], vl4[4];
                ldm_x4_t(vh4, sw_addr(svh, vrow, vun));
                ldm_x4_t(vl4, sw_addr(svl, vrow, vun));
                const int d0 = 2 * jp, d1 = 2 * jp + 1;
                mma16816(O[d0], pah, vh4[0], vh4[1]);
                mma16816(O[d0], pal, vh4[0], vh4[1]);
                mma16816(O[d0], pah, vl4[0], vl4[1]);
                mma16816(O[d1], pah, vh4[2], vh4[3]);
                mma16816(O[d1], pal, vh4[2], vh4[3]);
                mma16816(O[d1], pah, vl4[2], vl4[3]);
            }
        }
    }

    // ---- epilogue: O /= l, write split-K3 layout into ys ----
    const float il0 = 1.f / l0, il1 = 1.f / l1;
    const size_t r0g = rowQ + w * 16 + gid;
    const size_t r1g = r0g + 8;
    #pragma unroll
    for (int j = 0; j < 4; j++) {
        int col = hoff + j * 8 + 2 * tig;
        {
            float x = O[j][0] * il0, y = O[j][1] * il0;
            __nv_bfloat162 hb = __floats2bfloat162_rn(x, y);
            float2 hf = __bfloat1622float2(hb);
            __nv_bfloat162 lb = __floats2bfloat162_rn(x - hf.x, y - hf.y);
            __nv_bfloat16* p = ys + r0g * K3_ + col;
            *(__nv_bfloat162*)(p)        = hb;
            *(__nv_bfloat162*)(p + 1024) = lb;
            *(__nv_bfloat162*)(p + 2048) = hb;
        }
        {
            float x = O[j][2] * il1, y = O[j][3] * il1;
            __nv_bfloat162 hb = __floats2bfloat162_rn(x, y);
            float2 hf = __bfloat1622float2(hb);
            __nv_bfloat162 lb = __floats2bfloat162_rn(x - hf.x, y - hf.y);
            __nv_bfloat16* p = ys + r1g * K3_ + col;
            *(__nv_bfloat162*)(p)        = hb;
            *(__nv_bfloat162*)(p + 1024) = lb;
            *(__nv_bfloat162*)(p + 2048) = hb;
        }
    }
}

// ---------------- launcher ----------------------------------------------------
extern "C" void kernel_launch(void* const* d_in, const int* in_sizes, int n_in,
                              void* d_out, int out_size) {
    const float* x     = (const float*)d_in[0];
    const float* Wq    = (const float*)d_in[1];
    const float* Wk    = (const float*)d_in[2];
    const float* Wv    = (const float*)d_in[3];
    const float* Wproj = (const float*)d_in[4];
    const float* gain  = (const float*)d_in[5];
    const float* cosb  = (const float*)d_in[6];
    const float* sinb  = (const float*)d_in[7];
    float* out = (float*)d_out;

    float *q, *k, *v;
    __nv_bfloat16 *xs, *ys, *wqkv, *wpro, *qhp, *qlp, *khp, *klp, *vhp, *vlp;
    cudaGetSymbolAddress((void**)&q, g_q);
    cudaGetSymbolAddress((void**)&k, g_k);
    cudaGetSymbolAddress((void**)&v, g_v);
    cudaGetSymbolAddress((void**)&xs, g_xs);
    cudaGetSymbolAddress((void**)&ys, g_ys);
    cudaGetSymbolAddress((void**)&wqkv, g_wqkv);
    cudaGetSymbolAddress((void**)&wpro, g_wpro);
    cudaGetSymbolAddress((void**)&qhp, g_qh);
    cudaGetSymbolAddress((void**)&qlp, g_ql);
    cudaGetSymbolAddress((void**)&khp, g_kh);
    cudaGetSymbolAddress((void**)&klp, g_kl);
    cudaGetSymbolAddress((void**)&vhp, g_vh);
    cudaGetSymbolAddress((void**)&vlp, g_vl);

    // split conversions
    split_acts<<<(M_ * D_) / 256, 256>>>(x, xs);
    split_wts<<<(D_ * D_) / 256, 256>>>(Wq, wqkv);
    split_wts<<<(D_ * D_) / 256, 256>>>(Wk, wqkv + (size_t)D_ * K3_);
    split_wts<<<(D_ * D_) / 256, 256>>>(Wv, wqkv + (size_t)2 * D_ * K3_);
    split_wts<<<(D_ * D_) / 256, 256>>>(Wproj, wpro);

    // fused QKV GEMM: N = 3072 -> q | k | v (fp32)
    gemm_bf16<<<dim3(3 * D_ / 128, M_ / 128), 256>>>(xs, wqkv, q, k, v);

    int nwarps = M_ * NH_;
    norm_rope_split<<<nwarps / 8, 256>>>(q, cosb, sinb, gain, 1, qhp, qlp);
    norm_rope_split<<<nwarps / 8, 256>>>(k, cosb, sinb, gain, 0, khp, klp);
    split_v<<<(M_ * D_) / 256, 256>>>(v, vhp, vlp);

    flash_tc<<<dim3(T_ / 64, B_ * NH_), 128>>>(qhp, qlp, khp, klp, vhp, vlp, ys);

    gemm_bf16<<<dim3(D_ / 128, M_ / 128), 256>>>(ys, wpro, out, out, out);
}

// round 15
// speedup vs baseline: 3.8750x; 1.2995x over previous
#include <cuda_runtime.h>
#include <cuda_fp16.h>
#include <math.h>
#include <stdint.h>

#define B_   2
#define T_   2048
#define D_   1024
#define NH_  32
#define HD_  32
#define M_   (B_ * T_)          // 4096 rows
#define K2_  2048               // split-fp16 concatenated K
#define ITERS_ (K2_ / 32)       // 64 k-chunks of 32

// ---------------- scratch (allocation-free: __device__ globals) --------------
__device__ float g_q[M_ * D_];
__device__ float g_k[M_ * D_];
__device__ float g_v[M_ * D_];
__device__ __half g_qh[M_ * D_], g_ql[M_ * D_];
__device__ __half g_kh[M_ * D_];
__device__ __half g_vh[M_ * D_];
__device__ __half g_xs[M_ * K2_];        // split x   [Ah|Al]
__device__ __half g_ys[M_ * K2_];        // split y   (written by flash)
__device__ __half g_wqkv[3 * D_ * K2_];  // [Wq;Wk;Wv] as [Wh|Wh]
__device__ __half g_wpro[D_ * K2_];      // Wproj as [Wh|Wh]

// ---------------- PTX helpers -------------------------------------------------
__device__ __forceinline__ uint32_t smem_u32(const void* p) {
    return (uint32_t)__cvta_generic_to_shared(p);
}
__device__ __forceinline__ void cp_async16(uint32_t saddr, const void* gaddr) {
    asm volatile("cp.async.cg.shared.global [%0], [%1], 16;" :: "r"(saddr), "l"(gaddr));
}
__device__ __forceinline__ void cp_commit() {
    asm volatile("cp.async.commit_group;");
}
__device__ __forceinline__ void cp_wait0() {
    asm volatile("cp.async.wait_group 0;");
}
__device__ __forceinline__ void ldm_x4(uint32_t* r, uint32_t a) {
    asm volatile("ldmatrix.sync.aligned.m8n8.x4.shared.b16 {%0,%1,%2,%3}, [%4];"
                 : "=r"(r[0]), "=r"(r[1]), "=r"(r[2]), "=r"(r[3]) : "r"(a));
}
__device__ __forceinline__ void ldm_x4_t(uint32_t* r, uint32_t a) {
    asm volatile("ldmatrix.sync.aligned.m8n8.x4.trans.shared.b16 {%0,%1,%2,%3}, [%4];"
                 : "=r"(r[0]), "=r"(r[1]), "=r"(r[2]), "=r"(r[3]) : "r"(a));
}
__device__ __forceinline__ void mma16816(float* d, const uint32_t* a, uint32_t b0, uint32_t b1) {
    asm volatile("mma.sync.aligned.m16n8k16.row.col.f32.f16.f16.f32 "
                 "{%0,%1,%2,%3}, {%4,%5,%6,%7}, {%8,%9}, {%0,%1,%2,%3};"
                 : "+f"(d[0]), "+f"(d[1]), "+f"(d[2]), "+f"(d[3])
                 : "r"(a[0]), "r"(a[1]), "r"(a[2]), "r"(a[3]), "r"(b0), "r"(b1));
}
// swizzled smem address: rows of 64B (4 x 16B units); unit ^= (row>>1)&3
__device__ __forceinline__ uint32_t sw_addr(uint32_t base, int row, int unit) {
    return base + row * 64 + ((unit ^ ((row >> 1) & 3)) << 4);
}
// pack two floats into hi(half2) + residual lo(half2)
__device__ __forceinline__ void pack_split(float x, float y, uint32_t& hi, uint32_t& lo) {
    __half2 hb = __floats2half2_rn(x, y);
    hi = *reinterpret_cast<uint32_t*>(&hb);
    float2 hf = __half22float2(hb);
    __half2 lb = __floats2half2_rn(x - hf.x, y - hf.y);
    lo = *reinterpret_cast<uint32_t*>(&lb);
}

// ---------------- split-fp16 conversion kernels --------------------------------
__global__ void __launch_bounds__(256) split_acts(const float* __restrict__ in,
                                                  __half* __restrict__ out) {
    int i = blockIdx.x * 256 + threadIdx.x;
    int r = i >> 10, c = i & 1023;
    float x = in[i];
    __half h = __float2half_rn(x);
    __half l = __float2half_rn(x - __half2float(h));
    __half* o = out + (size_t)r * K2_ + c;
    o[0] = h; o[1024] = l;
}
__global__ void __launch_bounds__(256) split_wts(const float* __restrict__ in,
                                                 __half* __restrict__ out) {
    int i = blockIdx.x * 256 + threadIdx.x;
    int r = i >> 10, c = i & 1023;
    __half h = __float2half_rn(in[i]);
    __half* o = out + (size_t)r * K2_ + c;
    o[0] = h; o[1024] = h;
}
__global__ void __launch_bounds__(256) cvt_v(const float* __restrict__ in,
                                             __half* __restrict__ oh) {
    int i = blockIdx.x * 256 + threadIdx.x;
    oh[i] = __float2half_rn(in[i]);
}

// ---------------- mma.sync fp16 GEMM: C[M,Ntot] = A'[M,K2] @ W'[Ntot,K2]^T -----
// 128x128x32 tiles, 8 warps (2x4), 3-stage cp.async ring, one sync per k-iter.
__global__ void __launch_bounds__(256)
gemm_fp16(const __half* __restrict__ Abf,
          const __half* __restrict__ Wbf,
          float* __restrict__ C0, float* __restrict__ C1, float* __restrict__ C2) {
    __shared__ __half sA[3][128 * 32];
    __shared__ __half sB[3][128 * 32];

    const int tid  = threadIdx.x;
    const int wid  = tid >> 5;
    const int lane = tid & 31;
    const int wm   = wid >> 2;
    const int wn   = wid & 3;
    const int m0   = blockIdx.y * 128;
    const int n0   = blockIdx.x * 128;

    const __half* Ag = Abf + (size_t)m0 * K2_;
    const __half* Wg = Wbf + (size_t)n0 * K2_;

    uint32_t sa[3] = { smem_u32(&sA[0][0]), smem_u32(&sA[1][0]), smem_u32(&sA[2][0]) };
    uint32_t sb[3] = { smem_u32(&sB[0][0]), smem_u32(&sB[1][0]), smem_u32(&sB[2][0]) };

    const int lrow0 = tid >> 1;
    const int lu0   = (tid & 1) << 1;

    float acc[4][4][4];
    #pragma unroll
    for (int i = 0; i < 4; i++)
        #pragma unroll
        for (int j = 0; j < 4; j++)
            #pragma unroll
            for (int e = 0; e < 4; e++) acc[i][j][e] = 0.f;

    #pragma unroll
    for (int st = 0; st < 2; st++) {
        #pragma unroll
        for (int u = 0; u < 2; u++) {
            int unit = lu0 + u;
            cp_async16(sw_addr(sa[st], lrow0, unit), Ag + (size_t)lrow0 * K2_ + st * 32 + unit * 8);
            cp_async16(sw_addr(sb[st], lrow0, unit), Wg + (size_t)lrow0 * K2_ + st * 32 + unit * 8);
        }
        cp_commit();
    }

    for (int it = 0; it < ITERS_; it++) {
        asm volatile("cp.async.wait_group 1;");
        __syncthreads();

        const int cur = it % 3;
        const uint32_t ca = sa[cur];
        const uint32_t cb = sb[cur];

        #pragma unroll
        for (int ks = 0; ks < 2; ks++) {
            uint32_t af[4][4];
            #pragma unroll
            for (int mi = 0; mi < 4; mi++) {
                int row = wm * 64 + mi * 16 + (lane & 15);
                int unit = ks * 2 + (lane >> 4);
                ldm_x4(af[mi], sw_addr(ca, row, unit));
            }
            uint32_t bfr[4][2];
            #pragma unroll
            for (int nh = 0; nh < 2; nh++) {
                int row = wn * 32 + nh * 16 + (lane & 7) + ((lane >> 4) << 3);
                int unit = ks * 2 + ((lane >> 3) & 1);
                uint32_t r4[4];
                ldm_x4(r4, sw_addr(cb, row, unit));
                bfr[nh * 2 + 0][0] = r4[0]; bfr[nh * 2 + 0][1] = r4[1];
                bfr[nh * 2 + 1][0] = r4[2]; bfr[nh * 2 + 1][1] = r4[3];
            }
            #pragma unroll
            for (int mi = 0; mi < 4; mi++)
                #pragma unroll
                for (int ni = 0; ni < 4; ni++)
                    mma16816(acc[mi][ni], af[mi], bfr[ni][0], bfr[ni][1]);
        }

        if (it + 2 < ITERS_) {
            const int nxt = (it + 2) % 3;
            #pragma unroll
            for (int u = 0; u < 2; u++) {
                int unit = lu0 + u;
                cp_async16(sw_addr(sa[nxt], lrow0, unit),
                           Ag + (size_t)lrow0 * K2_ + (it + 2) * 32 + unit * 8);
                cp_async16(sw_addr(sb[nxt], lrow0, unit),
                           Wg + (size_t)lrow0 * K2_ + (it + 2) * 32 + unit * 8);
            }
        }
        cp_commit();
    }

    const int region = n0 >> 10;
    float* Cb = (region == 0) ? C0 : ((region == 1) ? C1 : C2);
    const int nloc = n0 & 1023;
    const int gid = lane >> 2;
    const int tig = lane & 3;
    #pragma unroll
    for (int mi = 0; mi < 4; mi++) {
        #pragma unroll
        for (int ni = 0; ni < 4; ni++) {
            int r0 = m0 + wm * 64 + mi * 16 + gid;
            int cc = nloc + wn * 32 + ni * 8 + tig * 2;
            *(float2*)&Cb[(size_t)r0 * D_ + cc]       = make_float2(acc[mi][ni][0], acc[mi][ni][1]);
            *(float2*)&Cb[(size_t)(r0 + 8) * D_ + cc] = make_float2(acc[mi][ni][2], acc[mi][ni][3]);
        }
    }
}

// ---------------- per-head RMSNorm + RoPE -> fp16 (hi, optional lo) ------------
// writeLoGain=1: apply gain and write lo residual (Q path); 0: hi only (K path)
__global__ void __launch_bounds__(256) norm_rope_split(const float* __restrict__ t,
                                                       const float* __restrict__ cosb,
                                                       const float* __restrict__ sinb,
                                                       const float* __restrict__ gain,
                                                       int writeLoGain,
                                                       __half* __restrict__ oh,
                                                       __half* __restrict__ ol) {
    int warp = (blockIdx.x * blockDim.x + threadIdx.x) >> 5;
    int lane = threadIdx.x & 31;
    if (warp >= M_ * NH_) return;
    int row = warp >> 5;
    int h   = warp & 31;
    int tp  = row & (T_ - 1);

    size_t idx = (size_t)row * D_ + h * HD_ + lane;
    float v = t[idx];

    float ss = v * v;
    #pragma unroll
    for (int off = 16; off > 0; off >>= 1)
        ss += __shfl_xor_sync(0xffffffffu, ss, off);

    float r = rsqrtf(ss * (1.0f / HD_) + 1e-6f);
    float vn = v * r;

    float other = __shfl_xor_sync(0xffffffffu, vn, 16);
    int dd = lane & 15;
    float c = cosb[tp * 16 + dd];
    float s = sinb[tp * 16 + dd];
    float out = (lane < 16) ? (vn * c - other * s) : (vn * c + other * s);
    if (writeLoGain) out *= gain[h];

    __half hb = __float2half_rn(out);
    oh[idx] = hb;
    if (writeLoGain) ol[idx] = __float2half_rn(out - __half2float(hb));
}

// ---------------- tensor-core causal flash attention ---------------------------
// grid (T/64, B*NH); 128 threads (4 warps); BQ=BK=64, HD=32; fp16 2-term split.
__global__ void __launch_bounds__(128)
flash_tc(const __half* __restrict__ qh, const __half* __restrict__ ql,
         const __half* __restrict__ kh, const __half* __restrict__ vh,
         __half* __restrict__ ys) {
    __shared__ __half sQh[64 * 32], sQl[64 * 32];
    __shared__ __half sKh[64 * 32], sVh[64 * 32];

    const int tid = threadIdx.x, lane = tid & 31, w = tid >> 5;
    const int gid = lane >> 2, tig = lane & 3;
    const int qb = blockIdx.x, bh = blockIdx.y;
    const size_t rowQ = (size_t)(bh >> 5) * T_ + qb * 64;
    const int hoff = (bh & 31) * HD_;
    const float scale = 0.17677669529663687f;   // 1/sqrt(32)

    const uint32_t sqh = smem_u32(sQh), sql = smem_u32(sQl);
    const uint32_t skh = smem_u32(sKh), svh = smem_u32(sVh);

    #pragma unroll
    for (int u = 0; u < 2; u++) {
        int id = tid * 2 + u;
        int un = id & 3, row = id >> 2;
        size_t go = (rowQ + row) * D_ + hoff + un * 8;
        cp_async16(sw_addr(sqh, row, un), qh + go);
        cp_async16(sw_addr(sql, row, un), ql + go);
    }
    cp_commit(); cp_wait0(); __syncthreads();

    uint32_t qaf[2][4], qlf[2][4];
    #pragma unroll
    for (int ks = 0; ks < 2; ks++) {
        uint32_t addr = sw_addr(sqh, w * 16 + (lane & 15), ks * 2 + (lane >> 4));
        ldm_x4(qaf[ks], addr);
        addr = sw_addr(sql, w * 16 + (lane & 15), ks * 2 + (lane >> 4));
        ldm_x4(qlf[ks], addr);
    }

    float m0 = -1e30f, m1 = -1e30f, l0 = 0.f, l1 = 0.f;
    float O[4][4];
    #pragma unroll
    for (int j = 0; j < 4; j++)
        #pragma unroll
        for (int e = 0; e < 4; e++) O[j][e] = 0.f;

    for (int jb = 0; jb <= qb; jb++) {
        __syncthreads();
        const size_t rowK = (size_t)(bh >> 5) * T_ + jb * 64;
        #pragma unroll
        for (int u = 0; u < 2; u++) {
            int id = tid * 2 + u;
            int un = id & 3, row = id >> 2;
            size_t go = (rowK + row) * D_ + hoff + un * 8;
            cp_async16(sw_addr(skh, row, un), kh + go);
            cp_async16(sw_addr(svh, row, un), vh + go);
        }
        cp_commit(); cp_wait0(); __syncthreads();

        // ---- S = Q K^T  (2-term: Qh·Kh + Ql·Kh) ----
        float st[8][4];
        #pragma unroll
        for (int j = 0; j < 8; j++)
            #pragma unroll
            for (int e = 0; e < 4; e++) st[j][e] = 0.f;

        #pragma unroll
        for (int g = 0; g < 4; g++) {
            #pragma unroll
            for (int ks = 0; ks < 2; ks++) {
                int brow = g * 16 + (lane & 7) + ((lane >> 4) << 3);
                int bun = ks * 2 + ((lane >> 3) & 1);
                uint32_t bh4[4];
                ldm_x4(bh4, sw_addr(skh, brow, bun));
                mma16816(st[2 * g],     qaf[ks], bh4[0], bh4[1]);
                mma16816(st[2 * g],     qlf[ks], bh4[0], bh4[1]);
                mma16816(st[2 * g + 1], qaf[ks], bh4[2], bh4[3]);
                mma16816(st[2 * g + 1], qlf[ks], bh4[2], bh4[3]);
            }
        }

        // ---- scale + causal mask ----
        const int rlo = w * 16 + gid, rhi = rlo + 8;
        if (jb == qb) {
            #pragma unroll
            for (int j = 0; j < 8; j++) {
                int c0 = j * 8 + 2 * tig;
                st[j][0] = (c0     <= rlo) ? st[j][0] * scale : -1e30f;
                st[j][1] = (c0 + 1 <= rlo) ? st[j][1] * scale : -1e30f;
                st[j][2] = (c0     <= rhi) ? st[j][2] * scale : -1e30f;
                st[j][3] = (c0 + 1 <= rhi) ? st[j][3] * scale : -1e30f;
            }
        } else {
            #pragma unroll
            for (int j = 0; j < 8; j++)
                #pragma unroll
                for (int e = 0; e < 4; e++) st[j][e] *= scale;
        }

        // ---- online softmax ----
        float mx0 = -1e30f, mx1 = -1e30f;
        #pragma unroll
        for (int j = 0; j < 8; j++) {
            mx0 = fmaxf(mx0, fmaxf(st[j][0], st[j][1]));
            mx1 = fmaxf(mx1, fmaxf(st[j][2], st[j][3]));
        }
        mx0 = fmaxf(mx0, __shfl_xor_sync(0xffffffffu, mx0, 1));
        mx0 = fmaxf(mx0, __shfl_xor_sync(0xffffffffu, mx0, 2));
        mx1 = fmaxf(mx1, __shfl_xor_sync(0xffffffffu, mx1, 1));
        mx1 = fmaxf(mx1, __shfl_xor_sync(0xffffffffu, mx1, 2));

        float mn0 = fmaxf(m0, mx0), mn1 = fmaxf(m1, mx1);
        float al0 = __expf(m0 - mn0), al1 = __expf(m1 - mn1);
        float s0 = 0.f, s1 = 0.f;
        #pragma unroll
        for (int j = 0; j < 8; j++) {
            st[j][0] = __expf(st[j][0] - mn0); s0 += st[j][0];
            st[j][1] = __expf(st[j][1] - mn0); s0 += st[j][1];
            st[j][2] = __expf(st[j][2] - mn1); s1 += st[j][2];
            st[j][3] = __expf(st[j][3] - mn1); s1 += st[j][3];
        }
        s0 += __shfl_xor_sync(0xffffffffu, s0, 1);
        s0 += __shfl_xor_sync(0xffffffffu, s0, 2);
        s1 += __shfl_xor_sync(0xffffffffu, s1, 1);
        s1 += __shfl_xor_sync(0xffffffffu, s1, 2);
        l0 = l0 * al0 + s0; l1 = l1 * al1 + s1;
        m0 = mn0; m1 = mn1;

        #pragma unroll
        for (int j = 0; j < 4; j++) {
            O[j][0] *= al0; O[j][1] *= al0;
            O[j][2] *= al1; O[j][3] *= al1;
        }

        // ---- O += P V  (2-term: Ph·Vh + Pl·Vh); V via ldmatrix.trans ----
        #pragma unroll
        for (int ks = 0; ks < 4; ks++) {
            const int t0 = 2 * ks, t1 = 2 * ks + 1;
            uint32_t pah[4], pal[4];
            pack_split(st[t0][0], st[t0][1], pah[0], pal[0]);
            pack_split(st[t0][2], st[t0][3], pah[1], pal[1]);
            pack_split(st[t1][0], st[t1][1], pah[2], pal[2]);
            pack_split(st[t1][2], st[t1][3], pah[3], pal[3]);

            #pragma unroll
            for (int jp = 0; jp < 2; jp++) {
                int vrow = ks * 16 + (lane & 15);
                int vun  = jp * 2 + (lane >> 4);
                uint32_t vh4[4];
                ldm_x4_t(vh4, sw_addr(svh, vrow, vun));
                const int d0 = 2 * jp, d1 = 2 * jp + 1;
                mma16816(O[d0], pah, vh4[0], vh4[1]);
                mma16816(O[d0], pal, vh4[0], vh4[1]);
                mma16816(O[d1], pah, vh4[2], vh4[3]);
                mma16816(O[d1], pal, vh4[2], vh4[3]);
            }
        }
    }

    // ---- epilogue: O /= l, write split-K2 layout into ys ----
    const float il0 = 1.f / l0, il1 = 1.f / l1;
    const size_t r0g = rowQ + w * 16 + gid;
    const size_t r1g = r0g + 8;
    #pragma unroll
    for (int j = 0; j < 4; j++) {
        int col = hoff + j * 8 + 2 * tig;
        {
            float x = O[j][0] * il0, y = O[j][1] * il0;
            __half2 hb = __floats2half2_rn(x, y);
            float2 hf = __half22float2(hb);
            __half2 lb = __floats2half2_rn(x - hf.x, y - hf.y);
            __half* p = ys + r0g * K2_ + col;
            *(__half2*)(p)        = hb;
            *(__half2*)(p + 1024) = lb;
        }
        {
            float x = O[j][2] * il1, y = O[j][3] * il1;
            __half2 hb = __floats2half2_rn(x, y);
            float2 hf = __half22float2(hb);
            __half2 lb = __floats2half2_rn(x - hf.x, y - hf.y);
            __half* p = ys + r1g * K2_ + col;
            *(__half2*)(p)        = hb;
            *(__half2*)(p + 1024) = lb;
        }
    }
}

// ---------------- launcher ----------------------------------------------------
extern "C" void kernel_launch(void* const* d_in, const int* in_sizes, int n_in,
                              void* d_out, int out_size) {
    const float* x     = (const float*)d_in[0];
    const float* Wq    = (const float*)d_in[1];
    const float* Wk    = (const float*)d_in[2];
    const float* Wv    = (const float*)d_in[3];
    const float* Wproj = (const float*)d_in[4];
    const float* gain  = (const float*)d_in[5];
    const float* cosb  = (const float*)d_in[6];
    const float* sinb  = (const float*)d_in[7];
    float* out = (float*)d_out;

    float *q, *k, *v;
    __half *xs, *ys, *wqkv, *wpro, *qhp, *qlp, *khp, *vhp;
    cudaGetSymbolAddress((void**)&q, g_q);
    cudaGetSymbolAddress((void**)&k, g_k);
    cudaGetSymbolAddress((void**)&v, g_v);
    cudaGetSymbolAddress((void**)&xs, g_xs);
    cudaGetSymbolAddress((void**)&ys, g_ys);
    cudaGetSymbolAddress((void**)&wqkv, g_wqkv);
    cudaGetSymbolAddress((void**)&wpro, g_wpro);
    cudaGetSymbolAddress((void**)&qhp, g_qh);
    cudaGetSymbolAddress((void**)&qlp, g_ql);
    cudaGetSymbolAddress((void**)&khp, g_kh);
    cudaGetSymbolAddress((void**)&vhp, g_vh);

    // split conversions
    split_acts<<<(M_ * D_) / 256, 256>>>(x, xs);
    split_wts<<<(D_ * D_) / 256, 256>>>(Wq, wqkv);
    split_wts<<<(D_ * D_) / 256, 256>>>(Wk, wqkv + (size_t)D_ * K2_);
    split_wts<<<(D_ * D_) / 256, 256>>>(Wv, wqkv + (size_t)2 * D_ * K2_);
    split_wts<<<(D_ * D_) / 256, 256>>>(Wproj, wpro);

    // fused QKV GEMM: N = 3072 -> q | k | v (fp32)
    gemm_fp16<<<dim3(3 * D_ / 128, M_ / 128), 256>>>(xs, wqkv, q, k, v);

    int nwarps = M_ * NH_;
    norm_rope_split<<<nwarps / 8, 256>>>(q, cosb, sinb, gain, 1, qhp, qlp);
    norm_rope_split<<<nwarps / 8, 256>>>(k, cosb, sinb, gain, 0, khp, khp);
    cvt_v<<<(M_ * D_) / 256, 256>>>(v, vhp);

    flash_tc<<<dim3(T_ / 64, B_ * NH_), 128>>>(qhp, qlp, khp, vhp, ys);

    gemm_fp16<<<dim3(D_ / 128, M_ / 128), 256>>>(ys, wpro, out, out, out);
}

// round 16
// speedup vs baseline: 4.0501x; 1.0452x over previous
#include <cuda_runtime.h>
#include <cuda_fp16.h>
#include <math.h>
#include <stdint.h>

#define B_   2
#define T_   2048
#define D_   1024
#define NH_  32
#define HD_  32
#define M_   (B_ * T_)          // 4096 rows
#define K2_  2048               // split-fp16 concatenated K
#define IT64_ (K2_ / 64)        // 32 k-chunks of 64

// ---------------- scratch (allocation-free: __device__ globals) --------------
__device__ float g_q[M_ * D_];
__device__ float g_k[M_ * D_];
__device__ float g_v[M_ * D_];
__device__ __half g_qh[M_ * D_], g_ql[M_ * D_];
__device__ __half g_kh[M_ * D_];
__device__ __half g_vh[M_ * D_];
__device__ __half g_xs[M_ * K2_];        // split x   [Ah|Al]
__device__ __half g_ys[M_ * K2_];        // split y   (written by flash)
__device__ __half g_wqkv[3 * D_ * K2_];  // [Wq;Wk;Wv] as [Wh|Wh]
__device__ __half g_wpro[D_ * K2_];      // Wproj as [Wh|Wh]

// ---------------- PTX helpers -------------------------------------------------
__device__ __forceinline__ uint32_t smem_u32(const void* p) {
    return (uint32_t)__cvta_generic_to_shared(p);
}
__device__ __forceinline__ void cp_async16(uint32_t saddr, const void* gaddr) {
    asm volatile("cp.async.cg.shared.global [%0], [%1], 16;" :: "r"(saddr), "l"(gaddr));
}
__device__ __forceinline__ void cp_commit() {
    asm volatile("cp.async.commit_group;");
}
__device__ __forceinline__ void ldm_x4(uint32_t* r, uint32_t a) {
    asm volatile("ldmatrix.sync.aligned.m8n8.x4.shared.b16 {%0,%1,%2,%3}, [%4];"
                 : "=r"(r[0]), "=r"(r[1]), "=r"(r[2]), "=r"(r[3]) : "r"(a));
}
__device__ __forceinline__ void ldm_x4_t(uint32_t* r, uint32_t a) {
    asm volatile("ldmatrix.sync.aligned.m8n8.x4.trans.shared.b16 {%0,%1,%2,%3}, [%4];"
                 : "=r"(r[0]), "=r"(r[1]), "=r"(r[2]), "=r"(r[3]) : "r"(a));
}
__device__ __forceinline__ void mma16816(float* d, const uint32_t* a, uint32_t b0, uint32_t b1) {
    asm volatile("mma.sync.aligned.m16n8k16.row.col.f32.f16.f16.f32 "
                 "{%0,%1,%2,%3}, {%4,%5,%6,%7}, {%8,%9}, {%0,%1,%2,%3};"
                 : "+f"(d[0]), "+f"(d[1]), "+f"(d[2]), "+f"(d[3])
                 : "r"(a[0]), "r"(a[1]), "r"(a[2]), "r"(a[3]), "r"(b0), "r"(b1));
}
// swizzled smem address for a 128x32-half tile: rows of 64B; unit ^= (row>>1)&3
__device__ __forceinline__ uint32_t sw_addr(uint32_t base, int row, int unit) {
    return base + row * 64 + ((unit ^ ((row >> 1) & 3)) << 4);
}
// pack two floats into hi(half2) + residual lo(half2)
__device__ __forceinline__ void pack_split(float x, float y, uint32_t& hi, uint32_t& lo) {
    __half2 hb = __floats2half2_rn(x, y);
    hi = *reinterpret_cast<uint32_t*>(&hb);
    float2 hf = __half22float2(hb);
    __half2 lb = __floats2half2_rn(x - hf.x, y - hf.y);
    lo = *reinterpret_cast<uint32_t*>(&lb);
}

// ---------------- split-fp16 conversion kernels --------------------------------
__global__ void __launch_bounds__(256) split_acts(const float* __restrict__ in,
                                                  __half* __restrict__ out) {
    int i = blockIdx.x * 256 + threadIdx.x;
    int r = i >> 10, c = i & 1023;
    float x = in[i];
    __half h = __float2half_rn(x);
    __half l = __float2half_rn(x - __half2float(h));
    __half* o = out + (size_t)r * K2_ + c;
    o[0] = h; o[1024] = l;
}
__global__ void __launch_bounds__(256) split_wts(const float* __restrict__ in,
                                                 __half* __restrict__ out) {
    int i = blockIdx.x * 256 + threadIdx.x;
    int r = i >> 10, c = i & 1023;
    __half h = __float2half_rn(in[i]);
    __half* o = out + (size_t)r * K2_ + c;
    o[0] = h; o[1024] = h;
}

// ---------------- mma.sync fp16 GEMM: C[M,Ntot] = A'[M,K2] @ W'[Ntot,K2]^T -----
// 128x128 CTA tile, k-chunk 64 (2 sub-chunks of 32), 3-stage cp.async ring,
// one __syncthreads per 64-k iter, 96KB dynamic smem.
// When Vh != nullptr and region==2, also emits fp16 copy of C (V tensor).
__global__ void __launch_bounds__(256)
gemm_fp16(const __half* __restrict__ Abf,
          const __half* __restrict__ Wbf,
          float* __restrict__ C0, float* __restrict__ C1, float* __restrict__ C2,
          __half* __restrict__ Vh) {
    extern __shared__ __half smem[];

    const int tid  = threadIdx.x;
    const int wid  = tid >> 5;
    const int lane = tid & 31;
    const int wm   = wid >> 2;
    const int wn   = wid & 3;
    const int m0   = blockIdx.y * 128;
    const int n0   = blockIdx.x * 128;

    const __half* Ag = Abf + (size_t)m0 * K2_;
    const __half* Wg = Wbf + (size_t)n0 * K2_;

    const uint32_t base = smem_u32(smem);
    // A stages: base + s*16384 bytes; B stages: base + 49152 + s*16384
    uint32_t aS[3] = { base, base + 16384, base + 32768 };
    uint32_t bS[3] = { base + 49152, base + 65536, base + 81920 };

    const int lrow0 = tid >> 1;          // 0..127
    const int lu0   = (tid & 1) << 1;    // 0 or 2

    float acc[4][4][4];
    #pragma unroll
    for (int i = 0; i < 4; i++)
        #pragma unroll
        for (int j = 0; j < 4; j++)
            #pragma unroll
            for (int e = 0; e < 4; e++) acc[i][j][e] = 0.f;

    // prologue: stages 0,1 (each = 2 sub-chunks of k=32)
    #pragma unroll
    for (int st = 0; st < 2; st++) {
        #pragma unroll
        for (int c = 0; c < 2; c++) {
            #pragma unroll
            for (int u = 0; u < 2; u++) {
                int unit = lu0 + u;
                int kof = st * 64 + c * 32 + unit * 8;
                cp_async16(sw_addr(aS[st] + c * 8192, lrow0, unit), Ag + (size_t)lrow0 * K2_ + kof);
                cp_async16(sw_addr(bS[st] + c * 8192, lrow0, unit), Wg + (size_t)lrow0 * K2_ + kof);
            }
        }
        cp_commit();
    }

    for (int it = 0; it < IT64_; it++) {
        asm volatile("cp.async.wait_group 1;");
        __syncthreads();

        const int cur = it % 3;

        #pragma unroll
        for (int c = 0; c < 2; c++) {
            const uint32_t ca = aS[cur] + c * 8192;
            const uint32_t cb = bS[cur] + c * 8192;
            #pragma unroll
            for (int ks = 0; ks < 2; ks++) {
                uint32_t af[4][4];
                #pragma unroll
                for (int mi = 0; mi < 4; mi++) {
                    int row = wm * 64 + mi * 16 + (lane & 15);
                    int unit = ks * 2 + (lane >> 4);
                    ldm_x4(af[mi], sw_addr(ca, row, unit));
                }
                uint32_t bfr[4][2];
                #pragma unroll
                for (int nh = 0; nh < 2; nh++) {
                    int row = wn * 32 + nh * 16 + (lane & 7) + ((lane >> 4) << 3);
                    int unit = ks * 2 + ((lane >> 3) & 1);
                    uint32_t r4[4];
                    ldm_x4(r4, sw_addr(cb, row, unit));
                    bfr[nh * 2 + 0][0] = r4[0]; bfr[nh * 2 + 0][1] = r4[1];
                    bfr[nh * 2 + 1][0] = r4[2]; bfr[nh * 2 + 1][1] = r4[3];
                }
                #pragma unroll
                for (int mi = 0; mi < 4; mi++)
                    #pragma unroll
                    for (int ni = 0; ni < 4; ni++)
                        mma16816(acc[mi][ni], af[mi], bfr[ni][0], bfr[ni][1]);
            }
        }

        if (it + 2 < IT64_) {
            const int nxt = (it + 2) % 3;
            #pragma unroll
            for (int c = 0; c < 2; c++) {
                #pragma unroll
                for (int u = 0; u < 2; u++) {
                    int unit = lu0 + u;
                    int kof = (it + 2) * 64 + c * 32 + unit * 8;
                    cp_async16(sw_addr(aS[nxt] + c * 8192, lrow0, unit),
                               Ag + (size_t)lrow0 * K2_ + kof);
                    cp_async16(sw_addr(bS[nxt] + c * 8192, lrow0, unit),
                               Wg + (size_t)lrow0 * K2_ + kof);
                }
            }
        }
        cp_commit();
    }

    const int region = n0 >> 10;
    float* Cb = (region == 0) ? C0 : ((region == 1) ? C1 : C2);
    const int nloc = n0 & 1023;
    const int gid = lane >> 2;
    const int tig = lane & 3;
    const bool emitV = (Vh != nullptr) && (region == 2);
    #pragma unroll
    for (int mi = 0; mi < 4; mi++) {
        #pragma unroll
        for (int ni = 0; ni < 4; ni++) {
            int r0 = m0 + wm * 64 + mi * 16 + gid;
            int cc = nloc + wn * 32 + ni * 8 + tig * 2;
            *(float2*)&Cb[(size_t)r0 * D_ + cc]       = make_float2(acc[mi][ni][0], acc[mi][ni][1]);
            *(float2*)&Cb[(size_t)(r0 + 8) * D_ + cc] = make_float2(acc[mi][ni][2], acc[mi][ni][3]);
            if (emitV) {
                __half2 v0 = __floats2half2_rn(acc[mi][ni][0], acc[mi][ni][1]);
                __half2 v1 = __floats2half2_rn(acc[mi][ni][2], acc[mi][ni][3]);
                *(__half2*)&Vh[(size_t)r0 * D_ + cc]       = v0;
                *(__half2*)&Vh[(size_t)(r0 + 8) * D_ + cc] = v1;
            }
        }
    }
}

// ---------------- fused per-head RMSNorm + RoPE for Q and K --------------------
// blockIdx.y: 0 -> Q (gain applied, writes hi+lo), 1 -> K (hi only)
__global__ void __launch_bounds__(256) norm_rope2(const float* __restrict__ qsrc,
                                                  const float* __restrict__ ksrc,
                                                  const float* __restrict__ cosb,
                                                  const float* __restrict__ sinb,
                                                  const float* __restrict__ gain,
                                                  __half* __restrict__ qh,
                                                  __half* __restrict__ ql,
                                                  __half* __restrict__ kh) {
    int warp = (blockIdx.x * blockDim.x + threadIdx.x) >> 5;
    int lane = threadIdx.x & 31;
    if (warp >= M_ * NH_) return;
    const int isQ = (blockIdx.y == 0);
    int row = warp >> 5;
    int h   = warp & 31;
    int tp  = row & (T_ - 1);

    size_t idx = (size_t)row * D_ + h * HD_ + lane;
    float v = isQ ? qsrc[idx] : ksrc[idx];

    float ss = v * v;
    #pragma unroll
    for (int off = 16; off > 0; off >>= 1)
        ss += __shfl_xor_sync(0xffffffffu, ss, off);

    float r = rsqrtf(ss * (1.0f / HD_) + 1e-6f);
    float vn = v * r;

    float other = __shfl_xor_sync(0xffffffffu, vn, 16);
    int dd = lane & 15;
    float c = cosb[tp * 16 + dd];
    float s = sinb[tp * 16 + dd];
    float out = (lane < 16) ? (vn * c - other * s) : (vn * c + other * s);

    if (isQ) {
        out *= gain[h];
        __half hb = __float2half_rn(out);
        qh[idx] = hb;
        ql[idx] = __float2half_rn(out - __half2float(hb));
    } else {
        kh[idx] = __float2half_rn(out);
    }
}

// ---------------- tensor-core causal flash attention ---------------------------
// grid (T/64, B*NH); 128 threads (4 warps); BQ=BK=64, HD=32; fp16 2-term split.
// Double-buffered K/V tiles (prefetch jb+1 during compute of jb).
__global__ void __launch_bounds__(128)
flash_tc(const __half* __restrict__ qh, const __half* __restrict__ ql,
         const __half* __restrict__ kh, const __half* __restrict__ vh,
         __half* __restrict__ ys) {
    __shared__ __half sQh[64 * 32], sQl[64 * 32];
    __shared__ __half sKh[2][64 * 32], sVh[2][64 * 32];

    const int tid = threadIdx.x, lane = tid & 31, w = tid >> 5;
    const int gid = lane >> 2, tig = lane & 3;
    const int qb = blockIdx.x, bh = blockIdx.y;
    const size_t rowQ = (size_t)(bh >> 5) * T_ + qb * 64;
    const int hoff = (bh & 31) * HD_;
    const float scale = 0.17677669529663687f;   // 1/sqrt(32)

    const uint32_t sqh = smem_u32(sQh), sql = smem_u32(sQl);
    const uint32_t skh[2] = { smem_u32(sKh[0]), smem_u32(sKh[1]) };
    const uint32_t svh[2] = { smem_u32(sVh[0]), smem_u32(sVh[1]) };

    // load Q tile halves
    #pragma unroll
    for (int u = 0; u < 2; u++) {
        int id = tid * 2 + u;
        int un = id & 3, row = id >> 2;
        size_t go = (rowQ + row) * D_ + hoff + un * 8;
        cp_async16(sw_addr(sqh, row, un), qh + go);
        cp_async16(sw_addr(sql, row, un), ql + go);
    }
    cp_commit();

    const size_t rowK0 = (size_t)(bh >> 5) * T_;
    // preload KV(0)
    #pragma unroll
    for (int u = 0; u < 2; u++) {
        int id = tid * 2 + u;
        int un = id & 3, row = id >> 2;
        size_t go = (rowK0 + row) * D_ + hoff + un * 8;
        cp_async16(sw_addr(skh[0], row, un), kh + go);
        cp_async16(sw_addr(svh[0], row, un), vh + go);
    }
    cp_commit();

    // Q fragments (need Q resident: wait for both groups, then sync)
    asm volatile("cp.async.wait_group 1;");
    __syncthreads();
    uint32_t qaf[2][4], qlf[2][4];
    #pragma unroll
    for (int ks = 0; ks < 2; ks++) {
        uint32_t addr = sw_addr(sqh, w * 16 + (lane & 15), ks * 2 + (lane >> 4));
        ldm_x4(qaf[ks], addr);
        addr = sw_addr(sql, w * 16 + (lane & 15), ks * 2 + (lane >> 4));
        ldm_x4(qlf[ks], addr);
    }

    float m0 = -1e30f, m1 = -1e30f, l0 = 0.f, l1 = 0.f;
    float O[4][4];
    #pragma unroll
    for (int j = 0; j < 4; j++)
        #pragma unroll
        for (int e = 0; e < 4; e++) O[j][e] = 0.f;

    for (int jb = 0; jb <= qb; jb++) {
        // ensure KV(jb) landed; all threads past previous compute
        asm volatile("cp.async.wait_group 0;");
        __syncthreads();

        const int buf = jb & 1;

        // prefetch KV(jb+1) into the other buffer (its readers are done)
        if (jb < qb) {
            const size_t rowK = rowK0 + (jb + 1) * 64;
            const int nb = buf ^ 1;
            #pragma unroll
            for (int u = 0; u < 2; u++) {
                int id = tid * 2 + u;
                int un = id & 3, row = id >> 2;
                size_t go = (rowK + row) * D_ + hoff + un * 8;
                cp_async16(sw_addr(skh[nb], row, un), kh + go);
                cp_async16(sw_addr(svh[nb], row, un), vh + go);
            }
            cp_commit();
        }

        // ---- S = Q K^T  (2-term: Qh·Kh + Ql·Kh) ----
        float st[8][4];
        #pragma unroll
        for (int j = 0; j < 8; j++)
            #pragma unroll
            for (int e = 0; e < 4; e++) st[j][e] = 0.f;

        #pragma unroll
        for (int g = 0; g < 4; g++) {
            #pragma unroll
            for (int ks = 0; ks < 2; ks++) {
                int brow = g * 16 + (lane & 7) + ((lane >> 4) << 3);
                int bun = ks * 2 + ((lane >> 3) & 1);
                uint32_t bh4[4];
                ldm_x4(bh4, sw_addr(skh[buf], brow, bun));
                mma16816(st[2 * g],     qaf[ks], bh4[0], bh4[1]);
                mma16816(st[2 * g],     qlf[ks], bh4[0], bh4[1]);
                mma16816(st[2 * g + 1], qaf[ks], bh4[2], bh4[3]);
                mma16816(st[2 * g + 1], qlf[ks], bh4[2], bh4[3]);
            }
        }

        // ---- scale + causal mask ----
        const int rlo = w * 16 + gid, rhi = rlo + 8;
        if (jb == qb) {
            #pragma unroll
            for (int j = 0; j < 8; j++) {
                int c0 = j * 8 + 2 * tig;
                st[j][0] = (c0     <= rlo) ? st[j][0] * scale : -1e30f;
                st[j][1] = (c0 + 1 <= rlo) ? st[j][1] * scale : -1e30f;
                st[j][2] = (c0     <= rhi) ? st[j][2] * scale : -1e30f;
                st[j][3] = (c0 + 1 <= rhi) ? st[j][3] * scale : -1e30f;
            }
        } else {
            #pragma unroll
            for (int j = 0; j < 8; j++)
                #pragma unroll
                for (int e = 0; e < 4; e++) st[j][e] *= scale;
        }

        // ---- online softmax ----
        float mx0 = -1e30f, mx1 = -1e30f;
        #pragma unroll
        for (int j = 0; j < 8; j++) {
            mx0 = fmaxf(mx0, fmaxf(st[j][0], st[j][1]));
            mx1 = fmaxf(mx1, fmaxf(st[j][2], st[j][3]));
        }
        mx0 = fmaxf(mx0, __shfl_xor_sync(0xffffffffu, mx0, 1));
        mx0 = fmaxf(mx0, __shfl_xor_sync(0xffffffffu, mx0, 2));
        mx1 = fmaxf(mx1, __shfl_xor_sync(0xffffffffu, mx1, 1));
        mx1 = fmaxf(mx1, __shfl_xor_sync(0xffffffffu, mx1, 2));

        float mn0 = fmaxf(m0, mx0), mn1 = fmaxf(m1, mx1);
        float al0 = __expf(m0 - mn0), al1 = __expf(m1 - mn1);
        float s0 = 0.f, s1 = 0.f;
        #pragma unroll
        for (int j = 0; j < 8; j++) {
            st[j][0] = __expf(st[j][0] - mn0); s0 += st[j][0];
            st[j][1] = __expf(st[j][1] - mn0); s0 += st[j][1];
            st[j][2] = __expf(st[j][2] - mn1); s1 += st[j][2];
            st[j][3] = __expf(st[j][3] - mn1); s1 += st[j][3];
        }
        s0 += __shfl_xor_sync(0xffffffffu, s0, 1);
        s0 += __shfl_xor_sync(0xffffffffu, s0, 2);
        s1 += __shfl_xor_sync(0xffffffffu, s1, 1);
        s1 += __shfl_xor_sync(0xffffffffu, s1, 2);
        l0 = l0 * al0 + s0; l1 = l1 * al1 + s1;
        m0 = mn0; m1 = mn1;

        #pragma unroll
        for (int j = 0; j < 4; j++) {
            O[j][0] *= al0; O[j][1] *= al0;
            O[j][2] *= al1; O[j][3] *= al1;
        }

        // ---- O += P V  (2-term: Ph·Vh + Pl·Vh); V via ldmatrix.trans ----
        #pragma unroll
        for (int ks = 0; ks < 4; ks++) {
            const int t0 = 2 * ks, t1 = 2 * ks + 1;
            uint32_t pah[4], pal[4];
            pack_split(st[t0][0], st[t0][1], pah[0], pal[0]);
            pack_split(st[t0][2], st[t0][3], pah[1], pal[1]);
            pack_split(st[t1][0], st[t1][1], pah[2], pal[2]);
            pack_split(st[t1][2], st[t1][3], pah[3], pal[3]);

            #pragma unroll
            for (int jp = 0; jp < 2; jp++) {
                int vrow = ks * 16 + (lane & 15);
                int vun  = jp * 2 + (lane >> 4);
                uint32_t vh4[4];
                ldm_x4_t(vh4, sw_addr(svh[buf], vrow, vun));
                const int d0 = 2 * jp, d1 = 2 * jp + 1;
                mma16816(O[d0], pah, vh4[0], vh4[1]);
                mma16816(O[d0], pal, vh4[0], vh4[1]);
                mma16816(O[d1], pah, vh4[2], vh4[3]);
                mma16816(O[d1], pal, vh4[2], vh4[3]);
            }
        }
    }

    // ---- epilogue: O /= l, write split-K2 layout into ys ----
    const float il0 = 1.f / l0, il1 = 1.f / l1;
    const size_t r0g = rowQ + w * 16 + gid;
    const size_t r1g = r0g + 8;
    #pragma unroll
    for (int j = 0; j < 4; j++) {
        int col = hoff + j * 8 + 2 * tig;
        {
            float x = O[j][0] * il0, y = O[j][1] * il0;
            __half2 hb = __floats2half2_rn(x, y);
            float2 hf = __half22float2(hb);
            __half2 lb = __floats2half2_rn(x - hf.x, y - hf.y);
            __half* p = ys + r0g * K2_ + col;
            *(__half2*)(p)        = hb;
            *(__half2*)(p + 1024) = lb;
        }
        {
            float x = O[j][2] * il1, y = O[j][3] * il1;
            __half2 hb = __floats2half2_rn(x, y);
            float2 hf = __half22float2(hb);
            __half2 lb = __floats2half2_rn(x - hf.x, y - hf.y);
            __half* p = ys + r1g * K2_ + col;
            *(__half2*)(p)        = hb;
            *(__half2*)(p + 1024) = lb;
        }
    }
}

// ---------------- launcher ----------------------------------------------------
extern "C" void kernel_launch(void* const* d_in, const int* in_sizes, int n_in,
                              void* d_out, int out_size) {
    const float* x     = (const float*)d_in[0];
    const float* Wq    = (const float*)d_in[1];
    const float* Wk    = (const float*)d_in[2];
    const float* Wv    = (const float*)d_in[3];
    const float* Wproj = (const float*)d_in[4];
    const float* gain  = (const float*)d_in[5];
    const float* cosb  = (const float*)d_in[6];
    const float* sinb  = (const float*)d_in[7];
    float* out = (float*)d_out;

    float *q, *k, *v;
    __half *xs, *ys, *wqkv, *wpro, *qhp, *qlp, *khp, *vhp;
    cudaGetSymbolAddress((void**)&q, g_q);
    cudaGetSymbolAddress((void**)&k, g_k);
    cudaGetSymbolAddress((void**)&v, g_v);
    cudaGetSymbolAddress((void**)&xs, g_xs);
    cudaGetSymbolAddress((void**)&ys, g_ys);
    cudaGetSymbolAddress((void**)&wqkv, g_wqkv);
    cudaGetSymbolAddress((void**)&wpro, g_wpro);
    cudaGetSymbolAddress((void**)&qhp, g_qh);
    cudaGetSymbolAddress((void**)&qlp, g_ql);
    cudaGetSymbolAddress((void**)&khp, g_kh);
    cudaGetSymbolAddress((void**)&vhp, g_vh);

    const int GSMEM = 96 * 1024;
    cudaFuncSetAttribute(gemm_fp16, cudaFuncAttributeMaxDynamicSharedMemorySize, GSMEM);

    // split conversions
    split_acts<<<(M_ * D_) / 256, 256>>>(x, xs);
    split_wts<<<(D_ * D_) / 256, 256>>>(Wq, wqkv);
    split_wts<<<(D_ * D_) / 256, 256>>>(Wk, wqkv + (size_t)D_ * K2_);
    split_wts<<<(D_ * D_) / 256, 256>>>(Wv, wqkv + (size_t)2 * D_ * K2_);
    split_wts<<<(D_ * D_) / 256, 256>>>(Wproj, wpro);

    // fused QKV GEMM: N = 3072 -> q | k | v (fp32) + fp16 V
    gemm_fp16<<<dim3(3 * D_ / 128, M_ / 128), 256, GSMEM>>>(xs, wqkv, q, k, v, vhp);

    int nwarps = M_ * NH_;
    norm_rope2<<<dim3(nwarps / 8, 2), 256>>>(q, k, cosb, sinb, gain, qhp, qlp, khp);

    flash_tc<<<dim3(T_ / 64, B_ * NH_), 128>>>(qhp, qlp, khp, vhp, ys);

    gemm_fp16<<<dim3(D_ / 128, M_ / 128), 256, GSMEM>>>(ys, wpro, out, out, out, nullptr);
}